// round 13
// baseline (speedup 1.0000x reference)
#include <cuda_runtime.h>
#include <cuda_bf16.h>
#include <cuda_fp16.h>
#include <math_constants.h>
#include <cstdint>
#include <cstddef>

#define S 2048
#define D 4096
#define HQ 32
#define HKV 8
#define HD 128
#define KV_W (HKV * HD) /* 1024 */
#define QD 6144         /* combined QKV output width */

// ---------------- scratch (no allocations allowed) ----------------
__device__ float g_QKV[(size_t)S * QD];  // Q | K | V fp32 (50 MB)

// int8 fixed-point planes: v ~= (v1*128 + v0) * scale
__device__ signed char g_Xq1[(size_t)S * D], g_Xq0[(size_t)S * D];
__device__ signed char g_Wq1[(size_t)QD * D], g_Wq0[(size_t)QD * D];  // [Wq;Wk;Wv]^T
__device__ signed char g_Woq1[(size_t)D * D], g_Woq0[(size_t)D * D];
__device__ signed char g_Aq1[(size_t)S * D], g_Aq0[(size_t)S * D];  // attn out

// pre-split fp16 K/V (2 fp16 per word) for attention
__device__ uint32_t g_Kh16[(size_t)S * 512], g_Kl16[(size_t)S * 512];
__device__ uint32_t g_Vh16[(size_t)S * 512], g_Vl16[(size_t)S * 512];

// scales: x/A plane bound 8 -> X = round(v*2048); w bound 0.125 -> round(w*131072)
// combined dequant factor = (8/16384)*(0.125/16384) = 2^-28
#define DEQ_FACTOR 3.725290298461914e-9f

// ---------------- helpers ----------------
__device__ __forceinline__ uint32_t smem_u32(const void* p) {
    uint32_t a;
    asm("{ .reg .u64 t; cvta.to.shared.u64 t, %1; cvt.u32.u64 %0, t; }"
        : "=r"(a) : "l"(p));
    return a;
}
// int8 mma, s32 accumulate (GEMMs)
__device__ __forceinline__ void mma16832i(int* d, const uint32_t* a,
                                          const uint32_t* b) {
    asm volatile(
        "mma.sync.aligned.m16n8k32.row.col.s32.s8.s8.s32 "
        "{%0,%1,%2,%3}, {%4,%5,%6,%7}, {%8,%9}, {%0,%1,%2,%3};"
        : "+r"(d[0]), "+r"(d[1]), "+r"(d[2]), "+r"(d[3])
        : "r"(a[0]), "r"(a[1]), "r"(a[2]), "r"(a[3]), "r"(b[0]), "r"(b[1]));
}
// fp16 mma (attention)
__device__ __forceinline__ void mma16816h(float* d, const uint32_t* a,
                                          const uint32_t* b) {
    asm volatile(
        "mma.sync.aligned.m16n8k16.row.col.f32.f16.f16.f32 "
        "{%0,%1,%2,%3}, {%4,%5,%6,%7}, {%8,%9}, {%0,%1,%2,%3};"
        : "+f"(d[0]), "+f"(d[1]), "+f"(d[2]), "+f"(d[3])
        : "r"(a[0]), "r"(a[1]), "r"(a[2]), "r"(a[3]), "r"(b[0]), "r"(b[1]));
}
__device__ __forceinline__ void cp16(uint32_t sdst, const void* gsrc) {
    asm volatile("cp.async.cg.shared.global [%0], [%1], 16;"
                 :: "r"(sdst), "l"(gsrc) : "memory");
}
#define CP_COMMIT() asm volatile("cp.async.commit_group;" ::: "memory")
#define CP_WAIT1() asm volatile("cp.async.wait_group 1;" ::: "memory")
#define CP_WAIT0() asm volatile("cp.async.wait_group 0;" ::: "memory")

__device__ __forceinline__ void ldm_x4(uint32_t* r, uint32_t a) {
    asm volatile("ldmatrix.sync.aligned.m8n8.x4.shared.b16 {%0,%1,%2,%3}, [%4];"
                 : "=r"(r[0]), "=r"(r[1]), "=r"(r[2]), "=r"(r[3]) : "r"(a));
}
__device__ __forceinline__ void ldm_x4_t(uint32_t* r, uint32_t a) {
    asm volatile("ldmatrix.sync.aligned.m8n8.x4.trans.shared.b16 {%0,%1,%2,%3}, [%4];"
                 : "=r"(r[0]), "=r"(r[1]), "=r"(r[2]), "=r"(r[3]) : "r"(a));
}
// fp32 -> packed fp16 hi/lo
__device__ __forceinline__ void split2h(float x, float y, uint32_t& hi, uint32_t& lo) {
    __half hx = __float2half_rn(x), hy = __float2half_rn(y);
    __half lx = __float2half_rn(x - __half2float(hx));
    __half ly = __float2half_rn(y - __half2float(hy));
    hi = (uint32_t)__half_as_ushort(hx) | ((uint32_t)__half_as_ushort(hy) << 16);
    lo = (uint32_t)__half_as_ushort(lx) | ((uint32_t)__half_as_ushort(ly) << 16);
}
// fp32 -> 15-bit fixed point -> two int8 planes
__device__ __forceinline__ void qsplit(float v, float s, int& hi, int& lo) {
    int X = __float2int_rn(v * s);
    X = min(16256, max(-16256, X));
    hi = (X + 64) >> 7;       // [-127, 127]
    lo = X - (hi << 7);       // [-64, 63]
}

// ---------------- quantization kernels ----------------
__global__ void xq_kernel(const float* __restrict__ x, signed char* __restrict__ q1,
                          signed char* __restrict__ q0, int n) {
    int i = blockIdx.x * blockDim.x + threadIdx.x;
    if (i < n) {
        int hi, lo;
        qsplit(x[i], 2048.f, hi, lo);
        q1[i] = (signed char)hi;
        q0[i] = (signed char)lo;
    }
}

// w [Kdim, Ndim] fp32 -> [Ndim, Kdim] int8 planes (transposed quantize)
__global__ void wq_kernel(const float* __restrict__ w, signed char* __restrict__ t1,
                          signed char* __restrict__ t0, int Kdim, int Ndim) {
    __shared__ float t[32][33];
    int n0 = blockIdx.x * 32, k0 = blockIdx.y * 32;
    int tx = threadIdx.x, ty = threadIdx.y;  // 32 x 8
#pragma unroll
    for (int i = 0; i < 32; i += 8)
        t[ty + i][tx] = w[(size_t)(k0 + ty + i) * Ndim + n0 + tx];
    __syncthreads();
#pragma unroll
    for (int i = 0; i < 32; i += 8) {
        int hi, lo;
        qsplit(t[tx][ty + i], 131072.f, hi, lo);
        size_t o = (size_t)(n0 + ty + i) * Kdim + k0 + tx;
        t1[o] = (signed char)hi;
        t0[o] = (signed char)lo;
    }
}

// ---------------- int8 fixed-point GEMM (IMMA m16n8k32) ----------------
// C[M,N] = ((A1*128+A0) . (B1*128+B0)) * 2^-28, exact int32 accumulation.
// CTA 128x128, K-chunk = 64 int8 (64B/row, stride 80), double buffered.
#define GCOMP (128 * 80)
#define GBUF (4 * GCOMP)
#define GEMM_SMEM (2 * GBUF) /* 81920 */

__device__ __forceinline__ void load_chunk_i8(
    const signed char* A1, const signed char* A0,
    const signed char* B1, const signed char* B0,
    int K, int kc, uint32_t sbuf, int tid) {
    const signed char* gp[4] = {A1, A0, B1, B0};
#pragma unroll
    for (int comp = 0; comp < 4; comp++) {
#pragma unroll
        for (int i = 0; i < 2; i++) {
            int id = tid + (i << 8);
            int r = id >> 2, c = id & 3;
            cp16(sbuf + comp * GCOMP + r * 80 + c * 16,
                 gp[comp] + (size_t)r * K + kc + c * 16);
        }
    }
}

__global__ void __launch_bounds__(256, 1) gemm_i8_kernel(
    const signed char* __restrict__ A1, const signed char* __restrict__ A0,
    const signed char* __restrict__ B1, const signed char* __restrict__ B0,
    float* __restrict__ C, int N, int K) {
    extern __shared__ char smem[];
    const uint32_t sb = smem_u32(smem);
    const int tid = threadIdx.x;
    const int wid = tid >> 5, lane = tid & 31;
    const int wm = wid >> 2, wn = wid & 3;
    const int g8 = lane >> 3, l8 = lane & 7;
    const int bm = blockIdx.y << 7, bn = blockIdx.x << 7;

    const signed char* pA1 = A1 + (size_t)bm * K;
    const signed char* pA0 = A0 + (size_t)bm * K;
    const signed char* pB1 = B1 + (size_t)bn * K;
    const signed char* pB0 = B0 + (size_t)bn * K;

    int acch[4][4][4], accm[4][4][4], accl[4][4][4];
#pragma unroll
    for (int mt = 0; mt < 4; mt++)
#pragma unroll
        for (int nt = 0; nt < 4; nt++)
#pragma unroll
            for (int i = 0; i < 4; i++) {
                acch[mt][nt][i] = 0;
                accm[mt][nt][i] = 0;
                accl[mt][nt][i] = 0;
            }

    const int NC = K >> 6;  // 64-elem chunks
    load_chunk_i8(pA1, pA0, pB1, pB0, K, 0, sb, tid);
    CP_COMMIT();

    const uint32_t aOff = (uint32_t)((wm * 64 + (g8 & 1) * 8 + l8) * 80 + (g8 >> 1) * 16);
    const uint32_t bOff = (uint32_t)((wn * 32 + (g8 >> 1) * 8 + l8) * 80 + (g8 & 1) * 16);

    for (int c = 0; c < NC; c++) {
        const uint32_t buf = sb + (uint32_t)(c & 1) * GBUF;
        if (c + 1 < NC) {
            load_chunk_i8(pA1, pA0, pB1, pB0, K, (c + 1) << 6,
                          sb + (uint32_t)((c + 1) & 1) * GBUF, tid);
            CP_COMMIT();
            CP_WAIT1();
        } else {
            CP_WAIT0();
        }
        __syncthreads();

#pragma unroll
        for (int ks = 0; ks < 2; ks++) {
            const uint32_t kb = (uint32_t)(ks * 32);
            uint32_t b1f[2][4], b0f[2][4];
#pragma unroll
            for (int ntp = 0; ntp < 2; ntp++) {
                uint32_t bo = buf + bOff + (uint32_t)(ntp * 16 * 80) + kb;
                ldm_x4(b1f[ntp], bo + 2 * GCOMP);
                ldm_x4(b0f[ntp], bo + 3 * GCOMP);
            }
#pragma unroll
            for (int mt = 0; mt < 4; mt++) {
                uint32_t a1f[4], a0f[4];
                uint32_t ao = buf + aOff + (uint32_t)(mt * 16 * 80) + kb;
                ldm_x4(a1f, ao);
                ldm_x4(a0f, ao + GCOMP);
#pragma unroll
                for (int ntp = 0; ntp < 2; ntp++) {
                    mma16832i(acch[mt][2 * ntp], a1f, b1f[ntp]);
                    mma16832i(accm[mt][2 * ntp], a1f, b0f[ntp]);
                    mma16832i(accm[mt][2 * ntp], a0f, b1f[ntp]);
                    mma16832i(accl[mt][2 * ntp], a0f, b0f[ntp]);
                    mma16832i(acch[mt][2 * ntp + 1], a1f, b1f[ntp] + 2);
                    mma16832i(accm[mt][2 * ntp + 1], a1f, b0f[ntp] + 2);
                    mma16832i(accm[mt][2 * ntp + 1], a0f, b1f[ntp] + 2);
                    mma16832i(accl[mt][2 * ntp + 1], a0f, b0f[ntp] + 2);
                }
            }
        }
        __syncthreads();
    }

    // epilogue: combine scales and dequantize
#pragma unroll
    for (int mt = 0; mt < 4; mt++) {
        int row = bm + wm * 64 + mt * 16 + (lane >> 2);
#pragma unroll
        for (int nt = 0; nt < 4; nt++) {
            int col = bn + wn * 32 + nt * 8 + (lane & 3) * 2;
            float v0 = ((float)acch[mt][nt][0] * 16384.f +
                        (float)accm[mt][nt][0] * 128.f + (float)accl[mt][nt][0]) *
                       DEQ_FACTOR;
            float v1 = ((float)acch[mt][nt][1] * 16384.f +
                        (float)accm[mt][nt][1] * 128.f + (float)accl[mt][nt][1]) *
                       DEQ_FACTOR;
            float v2 = ((float)acch[mt][nt][2] * 16384.f +
                        (float)accm[mt][nt][2] * 128.f + (float)accl[mt][nt][2]) *
                       DEQ_FACTOR;
            float v3 = ((float)acch[mt][nt][3] * 16384.f +
                        (float)accm[mt][nt][3] * 128.f + (float)accl[mt][nt][3]) *
                       DEQ_FACTOR;
            *(float2*)(C + (size_t)row * N + col) = make_float2(v0, v1);
            *(float2*)(C + (size_t)(row + 8) * N + col) = make_float2(v2, v3);
        }
    }
}

// ---------------- RoPE on Q (in g_QKV), fp32 in-place ----------------
__global__ void rope_q_kernel(float* __restrict__ QKV,
                              const float* __restrict__ cosv,
                              const float* __restrict__ sinv) {
    const int qn = S * HQ * (HD / 2);
    int idx = blockIdx.x * blockDim.x + threadIdx.x;
    if (idx < qn) {
        int i = idx & 63;
        int h = (idx >> 6) & (HQ - 1);
        int s = idx >> 11;
        float c = cosv[(s << 6) + i];
        float sn = sinv[(s << 6) + i];
        float2* p = (float2*)(QKV + (size_t)s * QD + h * HD) + i;
        float2 v = *p;
        *p = make_float2(v.x * c - v.y * sn, v.x * sn + v.y * c);
    }
}

// ---------------- K rope + fp16 hi/lo split; V fp16 hi/lo split ----------------
__global__ void kvsplit_kernel(const float* __restrict__ QKV,
                               const float* __restrict__ cosv,
                               const float* __restrict__ sinv,
                               uint32_t* __restrict__ Kh, uint32_t* __restrict__ Kl,
                               uint32_t* __restrict__ Vh, uint32_t* __restrict__ Vl) {
    const int n = S * 512;  // pairs per tensor
    int idx = blockIdx.x * blockDim.x + threadIdx.x;
    if (idx < n) {  // K with rope
        int pc = idx & 511, s = idx >> 9;
        int i = pc & 63;
        float2 v = *(const float2*)(QKV + (size_t)s * QD + 4096 + pc * 2);
        float c = cosv[(s << 6) + i], sn = sinv[(s << 6) + i];
        uint32_t hw, lw;
        split2h(v.x * c - v.y * sn, v.x * sn + v.y * c, hw, lw);
        Kh[idx] = hw;
        Kl[idx] = lw;
    } else if (idx < 2 * n) {  // V
        int t = idx - n;
        int pc = t & 511, s = t >> 9;
        float2 v = *(const float2*)(QKV + (size_t)s * QD + 5120 + pc * 2);
        uint32_t hw, lw;
        split2h(v.x, v.y, hw, lw);
        Vh[t] = hw;
        Vl[t] = lw;
    }
}

// ---------------- Flash attention, fp16 mma, pre-split K/V + double buffer ----
#define QK_STR 272 /* bytes per 128-col f16 row */
#define P_STR 144
#define PS_STR 68
#define OFF_QH 0
#define OFF_QL 17408
#define OFF_KV 34816
#define KV_STAGE 69632
#define ST_KH 0
#define ST_KL 17408
#define ST_VH 34816
#define ST_VL 52224
#define OFF_PS 174080
#define OFF_PB 191488
#define OFF_PL 200704
#define OFF_FR 209920
#define OFF_IL 210176
#define ATTN2_SMEM 210432

__device__ __forceinline__ void issue_kv(const uint32_t* const* gp, int k0, int kvh,
                                         uint32_t stage, int tid) {
#pragma unroll
    for (int a = 0; a < 4; a++)
#pragma unroll
        for (int j = 0; j < 4; j++) {
            int id = tid + (j << 8);
            int r = id >> 4, c = id & 15;
            cp16(stage + a * 17408 + r * QK_STR + c * 16,
                 gp[a] + (size_t)(k0 + r) * 512 + kvh * 64 + c * 4);
        }
}

__global__ __launch_bounds__(256) void attn_mma_kernel(
    const float* __restrict__ Qg, const uint32_t* __restrict__ Khg,
    const uint32_t* __restrict__ Klg, const uint32_t* __restrict__ Vhg,
    const uint32_t* __restrict__ Vlg,
    signed char* __restrict__ Aq1, signed char* __restrict__ Aq0) {
    extern __shared__ char smb[];
    const uint32_t sb = smem_u32(smb);
    const int tid = threadIdx.x, wid = tid >> 5, lane = tid & 31;
    const int h = blockIdx.y, q0 = blockIdx.x * 64, kvh = h >> 2;
    const int wm = wid & 3, wn = wid >> 2;
    const int g8 = lane >> 3, l8 = lane & 7;
    const int row = tid >> 2, lr = tid & 3;
    const int r0 = wm * 16 + (lane >> 2);
    const float scale = 0.08838834764831845f;  // 1/sqrt(128)

    float* fRp = (float*)(smb + OFF_FR);
    float* iLp = (float*)(smb + OFF_IL);

    // load Q tile, fp16 hi/lo split
    for (int i = tid; i < 2048; i += 256) {
        int r = i >> 5, c4 = (i & 31) << 2;
        float4 q = *(const float4*)(Qg + (size_t)(q0 + r) * QD + h * HD + c4);
        uint32_t h0, l0, h1, l1;
        split2h(q.x, q.y, h0, l0);
        split2h(q.z, q.w, h1, l1);
        *(uint2*)(smb + OFF_QH + r * QK_STR + c4 * 2) = make_uint2(h0, h1);
        *(uint2*)(smb + OFF_QL + r * QK_STR + c4 * 2) = make_uint2(l0, l1);
    }

    float m_i = -CUDART_INF_F, l_i = 0.f;
    float oacc[8][4];
#pragma unroll
    for (int nt = 0; nt < 8; nt++)
#pragma unroll
        for (int i = 0; i < 4; i++) oacc[nt][i] = 0.f;

    const uint32_t aRow = (uint32_t)(wm * 16 + (g8 & 1) * 8 + l8);
    const uint32_t qhB = sb + OFF_QH + aRow * QK_STR;
    const uint32_t qlB = sb + OFF_QL + aRow * QK_STR;
    const uint32_t phB = sb + OFF_PB + aRow * P_STR;
    const uint32_t plB = sb + OFF_PL + aRow * P_STR;
    const uint32_t aColOfs = (uint32_t)((g8 >> 1) * 8) * 2;

    const uint32_t* gp[4] = {Khg, Klg, Vhg, Vlg};
    issue_kv(gp, 0, kvh, sb + OFF_KV, tid);
    CP_COMMIT();

    for (int k0 = 0; k0 <= q0; k0 += 64) {
        const int it = k0 >> 6;
        const uint32_t stage = sb + OFF_KV + (uint32_t)(it & 1) * KV_STAGE;
        __syncthreads();
        if (k0 + 64 <= q0) {
            issue_kv(gp, k0 + 64, kvh, sb + OFF_KV + (uint32_t)((it + 1) & 1) * KV_STAGE,
                     tid);
            CP_COMMIT();
            CP_WAIT1();
        } else {
            CP_WAIT0();
        }
        __syncthreads();

        // ---- scores: S = Q K^T (Qh*Kh + Qh*Kl + Ql*Kh) ----
        float sacc[4][4];
#pragma unroll
        for (int nt = 0; nt < 4; nt++)
#pragma unroll
            for (int i = 0; i < 4; i++) sacc[nt][i] = 0.f;

#pragma unroll
        for (int ks = 0; ks < 8; ks++) {
            uint32_t aH[4], aL[4];
            uint32_t co = (uint32_t)(ks * 16) * 2 + aColOfs;
            ldm_x4(aH, qhB + co);
            ldm_x4(aL, qlB + co);
#pragma unroll
            for (int ntp = 0; ntp < 2; ntp++) {
                uint32_t bH[4], bL[4];
                uint32_t nrow = (uint32_t)(wn * 32 + ntp * 16 + (g8 >> 1) * 8 + l8);
                uint32_t kof = (uint32_t)(ks * 16 + (g8 & 1) * 8) * 2;
                ldm_x4(bH, stage + ST_KH + nrow * QK_STR + kof);
                ldm_x4(bL, stage + ST_KL + nrow * QK_STR + kof);
                mma16816h(sacc[2 * ntp], aH, bH);
                mma16816h(sacc[2 * ntp], aH, bL);
                mma16816h(sacc[2 * ntp], aL, bH);
                mma16816h(sacc[2 * ntp + 1], aH, bH + 2);
                mma16816h(sacc[2 * ntp + 1], aH, bL + 2);
                mma16816h(sacc[2 * ntp + 1], aL, bH + 2);
            }
        }
        {
            float* Ps = (float*)(smb + OFF_PS);
            int qr0 = q0 + r0, qr1 = qr0 + 8;
#pragma unroll
            for (int nt = 0; nt < 4; nt++) {
                int c = wn * 32 + nt * 8 + (lane & 3) * 2;
                int kc = k0 + c;
                Ps[r0 * PS_STR + c] = (kc <= qr0) ? sacc[nt][0] * scale : -CUDART_INF_F;
                Ps[r0 * PS_STR + c + 1] =
                    (kc + 1 <= qr0) ? sacc[nt][1] * scale : -CUDART_INF_F;
                Ps[(r0 + 8) * PS_STR + c] =
                    (kc <= qr1) ? sacc[nt][2] * scale : -CUDART_INF_F;
                Ps[(r0 + 8) * PS_STR + c + 1] =
                    (kc + 1 <= qr1) ? sacc[nt][3] * scale : -CUDART_INF_F;
            }
        }
        __syncthreads();

        // ---- online softmax ----
        {
            const float* prow = (const float*)(smb + OFF_PS) + row * PS_STR + lr * 16;
            float pv[16];
            float rmax = -CUDART_INF_F;
#pragma unroll
            for (int j = 0; j < 16; j++) {
                pv[j] = prow[j];
                rmax = fmaxf(rmax, pv[j]);
            }
            rmax = fmaxf(rmax, __shfl_xor_sync(0xffffffff, rmax, 1));
            rmax = fmaxf(rmax, __shfl_xor_sync(0xffffffff, rmax, 2));
            float m_new = fmaxf(m_i, rmax);
            float rsum = 0.f;
#pragma unroll
            for (int j = 0; j < 16; j++) {
                pv[j] = __expf(pv[j] - m_new);
                rsum += pv[j];
            }
            rsum += __shfl_xor_sync(0xffffffff, rsum, 1);
            rsum += __shfl_xor_sync(0xffffffff, rsum, 2);
            float f = __expf(m_i - m_new);
            l_i = l_i * f + rsum;
            m_i = m_new;
            if (lr == 0) fRp[row] = f;
#pragma unroll
            for (int j = 0; j < 8; j++) {
                uint32_t hw, lw;
                split2h(pv[2 * j], pv[2 * j + 1], hw, lw);
                int po = row * P_STR + (lr * 16 + 2 * j) * 2;
                *(uint32_t*)(smb + OFF_PB + po) = hw;
                *(uint32_t*)(smb + OFF_PL + po) = lw;
            }
        }
        __syncthreads();

        // ---- PV: O = (Ph+Pl)*(Vh+Vl) less lo*lo, online rescale ----
        {
            float f0 = fRp[r0], f1 = fRp[r0 + 8];
#pragma unroll
            for (int nt = 0; nt < 8; nt++) {
                oacc[nt][0] *= f0;
                oacc[nt][1] *= f0;
                oacc[nt][2] *= f1;
                oacc[nt][3] *= f1;
            }
#pragma unroll
            for (int ks = 0; ks < 4; ks++) {
                uint32_t aP[4], aPl[4];
                uint32_t po = (uint32_t)(ks * 16) * 2 + ((uint32_t)((g8 >> 1) * 8) * 2);
                ldm_x4(aP, phB + po);
                ldm_x4(aPl, plB + po);
                uint32_t krow = (uint32_t)(ks * 16 + (g8 & 1) * 8 + l8);
#pragma unroll
                for (int ntp = 0; ntp < 4; ntp++) {
                    uint32_t bH[4], bL[4];
                    uint32_t ncol = (uint32_t)(wn * 64 + ntp * 16 + (g8 >> 1) * 8);
                    ldm_x4_t(bH, stage + ST_VH + krow * QK_STR + ncol * 2);
                    ldm_x4_t(bL, stage + ST_VL + krow * QK_STR + ncol * 2);
                    mma16816h(oacc[2 * ntp], aP, bH);
                    mma16816h(oacc[2 * ntp], aP, bL);
                    mma16816h(oacc[2 * ntp], aPl, bH);
                    mma16816h(oacc[2 * ntp + 1], aP, bH + 2);
                    mma16816h(oacc[2 * ntp + 1], aP, bL + 2);
                    mma16816h(oacc[2 * ntp + 1], aPl, bH + 2);
                }
            }
        }
    }

    if (lr == 0) iLp[row] = 1.f / l_i;
    __syncthreads();

    // finalize: scale by 1/l, quantize to int8 planes (feeds wo GEMM)
    {
        float i0 = iLp[r0], i1 = iLp[r0 + 8];
#pragma unroll
        for (int nt = 0; nt < 8; nt++) {
            int col = h * HD + wn * 64 + nt * 8 + (lane & 3) * 2;
            size_t o0 = (size_t)(q0 + r0) * D + col;
            size_t o1 = (size_t)(q0 + r0 + 8) * D + col;
            int ha, la, hb, lb;
            qsplit(oacc[nt][0] * i0, 2048.f, ha, la);
            qsplit(oacc[nt][1] * i0, 2048.f, hb, lb);
            *(char2*)(Aq1 + o0) = make_char2((signed char)ha, (signed char)hb);
            *(char2*)(Aq0 + o0) = make_char2((signed char)la, (signed char)lb);
            qsplit(oacc[nt][2] * i1, 2048.f, ha, la);
            qsplit(oacc[nt][3] * i1, 2048.f, hb, lb);
            *(char2*)(Aq1 + o1) = make_char2((signed char)ha, (signed char)hb);
            *(char2*)(Aq0 + o1) = make_char2((signed char)la, (signed char)lb);
        }
    }
}

// ---------------- launch ----------------
extern "C" void kernel_launch(void* const* d_in, const int* in_sizes, int n_in,
                              void* d_out, int out_size) {
    const float* x = (const float*)d_in[0];
    const float* wq = (const float*)d_in[1];
    const float* wk = (const float*)d_in[2];
    const float* wv = (const float*)d_in[3];
    const float* wo = (const float*)d_in[4];
    const float* cosv = (const float*)d_in[5];
    const float* sinv = (const float*)d_in[6];
    float* out = (float*)d_out;

    float* pQKV;
    cudaGetSymbolAddress((void**)&pQKV, g_QKV);
    signed char *pXq1, *pXq0, *pWq1, *pWq0, *pWoq1, *pWoq0, *pAq1, *pAq0;
    cudaGetSymbolAddress((void**)&pXq1, g_Xq1);
    cudaGetSymbolAddress((void**)&pXq0, g_Xq0);
    cudaGetSymbolAddress((void**)&pWq1, g_Wq1);
    cudaGetSymbolAddress((void**)&pWq0, g_Wq0);
    cudaGetSymbolAddress((void**)&pWoq1, g_Woq1);
    cudaGetSymbolAddress((void**)&pWoq0, g_Woq0);
    cudaGetSymbolAddress((void**)&pAq1, g_Aq1);
    cudaGetSymbolAddress((void**)&pAq0, g_Aq0);
    uint32_t *pKh, *pKl, *pVh, *pVl;
    cudaGetSymbolAddress((void**)&pKh, g_Kh16);
    cudaGetSymbolAddress((void**)&pKl, g_Kl16);
    cudaGetSymbolAddress((void**)&pVh, g_Vh16);
    cudaGetSymbolAddress((void**)&pVl, g_Vl16);

    cudaFuncSetAttribute(gemm_i8_kernel, cudaFuncAttributeMaxDynamicSharedMemorySize,
                         GEMM_SMEM);
    cudaFuncSetAttribute(attn_mma_kernel,
                         cudaFuncAttributeMaxDynamicSharedMemorySize, ATTN2_SMEM);

    // quantize x + transposed weights ([Wq;Wk;Wv] combined, Wo separate)
    {
        int n = S * D;
        xq_kernel<<<(n + 255) / 256, 256>>>(x, pXq1, pXq0, n);
    }
    wq_kernel<<<dim3(D / 32, D / 32), dim3(32, 8)>>>(wq, pWq1, pWq0, D, D);
    wq_kernel<<<dim3(KV_W / 32, D / 32), dim3(32, 8)>>>(
        wk, pWq1 + (size_t)4096 * D, pWq0 + (size_t)4096 * D, D, KV_W);
    wq_kernel<<<dim3(KV_W / 32, D / 32), dim3(32, 8)>>>(
        wv, pWq1 + (size_t)5120 * D, pWq0 + (size_t)5120 * D, D, KV_W);
    wq_kernel<<<dim3(D / 32, D / 32), dim3(32, 8)>>>(wo, pWoq1, pWoq0, D, D);

    // combined QKV projection (int8 IMMA GEMM, N=6144)
    gemm_i8_kernel<<<dim3(QD / 128, S / 128), 256, GEMM_SMEM>>>(
        pXq1, pXq0, pWq1, pWq0, pQKV, QD, D);

    // RoPE on Q; K rope + fp16 pre-split; V fp16 pre-split
    {
        int qn = S * HQ * (HD / 2);
        rope_q_kernel<<<(qn + 255) / 256, 256>>>(pQKV, cosv, sinv);
        int kvn = 2 * S * 512;
        kvsplit_kernel<<<(kvn + 255) / 256, 256>>>(pQKV, cosv, sinv, pKh, pKl, pVh,
                                                   pVl);
    }

    // attention (fp16 mma; epilogue quantizes O to int8 planes)
    attn_mma_kernel<<<dim3(S / 64, HQ), 256, ATTN2_SMEM>>>(pQKV, pKh, pKl, pVh, pVl,
                                                           pAq1, pAq0);

    // output projection (int8 IMMA GEMM)
    gemm_i8_kernel<<<dim3(D / 128, S / 128), 256, GEMM_SMEM>>>(
        pAq1, pAq0, pWoq1, pWoq0, out, D, D);
}

// round 14
// speedup vs baseline: 4.1598x; 4.1598x over previous
#include <cuda_runtime.h>
#include <cuda_bf16.h>
#include <cuda_fp16.h>
#include <math_constants.h>
#include <cstdint>
#include <cstddef>

#define S 2048
#define D 4096
#define HQ 32
#define HKV 8
#define HD 128
#define KV_W (HKV * HD) /* 1024 */
#define QD 6144         /* combined QKV output width */

// ---------------- scratch (no allocations allowed) ----------------
__device__ float g_QKV[(size_t)S * QD];  // Q | K | V fp32 (50 MB)

// bf16 hi/lo split buffers
__device__ __nv_bfloat16 g_Xh[(size_t)S * D], g_Xl[(size_t)S * D];  // x, then attn out
__device__ __nv_bfloat16 g_Wh[(size_t)QD * D], g_Wl[(size_t)QD * D];  // [Wq;Wk;Wv] T
__device__ __nv_bfloat16 g_Woh[(size_t)D * D], g_Wol[(size_t)D * D];

// pre-split fp16 K/V (2 fp16 per word)
__device__ uint32_t g_Kh16[(size_t)S * 512], g_Kl16[(size_t)S * 512];
__device__ uint32_t g_Vh16[(size_t)S * 512], g_Vl16[(size_t)S * 512];

// ---------------- mma.sync / cp.async / ldmatrix helpers ----------------
__device__ __forceinline__ uint32_t smem_u32(const void* p) {
    uint32_t a;
    asm("{ .reg .u64 t; cvta.to.shared.u64 t, %1; cvt.u32.u64 %0, t; }"
        : "=r"(a) : "l"(p));
    return a;
}
// bf16 mma (GEMMs)
__device__ __forceinline__ void mma16816(float* d, const uint32_t* a,
                                         const uint32_t* b) {
    asm volatile(
        "mma.sync.aligned.m16n8k16.row.col.f32.bf16.bf16.f32 "
        "{%0,%1,%2,%3}, {%4,%5,%6,%7}, {%8,%9}, {%0,%1,%2,%3};"
        : "+f"(d[0]), "+f"(d[1]), "+f"(d[2]), "+f"(d[3])
        : "r"(a[0]), "r"(a[1]), "r"(a[2]), "r"(a[3]), "r"(b[0]), "r"(b[1]));
}
// fp16 mma (attention)
__device__ __forceinline__ void mma16816h(float* d, const uint32_t* a,
                                          const uint32_t* b) {
    asm volatile(
        "mma.sync.aligned.m16n8k16.row.col.f32.f16.f16.f32 "
        "{%0,%1,%2,%3}, {%4,%5,%6,%7}, {%8,%9}, {%0,%1,%2,%3};"
        : "+f"(d[0]), "+f"(d[1]), "+f"(d[2]), "+f"(d[3])
        : "r"(a[0]), "r"(a[1]), "r"(a[2]), "r"(a[3]), "r"(b[0]), "r"(b[1]));
}
__device__ __forceinline__ void cp16(uint32_t sdst, const void* gsrc) {
    asm volatile("cp.async.cg.shared.global [%0], [%1], 16;"
                 :: "r"(sdst), "l"(gsrc) : "memory");
}
#define CP_COMMIT() asm volatile("cp.async.commit_group;" ::: "memory")
#define CP_WAIT1() asm volatile("cp.async.wait_group 1;" ::: "memory")
#define CP_WAIT0() asm volatile("cp.async.wait_group 0;" ::: "memory")

__device__ __forceinline__ void ldm_x4(uint32_t* r, uint32_t a) {
    asm volatile("ldmatrix.sync.aligned.m8n8.x4.shared.b16 {%0,%1,%2,%3}, [%4];"
                 : "=r"(r[0]), "=r"(r[1]), "=r"(r[2]), "=r"(r[3]) : "r"(a));
}
__device__ __forceinline__ void ldm_x4_t(uint32_t* r, uint32_t a) {
    asm volatile("ldmatrix.sync.aligned.m8n8.x4.trans.shared.b16 {%0,%1,%2,%3}, [%4];"
                 : "=r"(r[0]), "=r"(r[1]), "=r"(r[2]), "=r"(r[3]) : "r"(a));
}

// split two fp32 into packed bf16 hi / lo words (low 16 = first element)
__device__ __forceinline__ void split2(float x, float y, uint32_t& hi, uint32_t& lo) {
    __nv_bfloat16 hx = __float2bfloat16(x), hy = __float2bfloat16(y);
    __nv_bfloat16 lx = __float2bfloat16(x - __bfloat162float(hx));
    __nv_bfloat16 ly = __float2bfloat16(y - __bfloat162float(hy));
    hi = (uint32_t)__bfloat16_as_ushort(hx) | ((uint32_t)__bfloat16_as_ushort(hy) << 16);
    lo = (uint32_t)__bfloat16_as_ushort(lx) | ((uint32_t)__bfloat16_as_ushort(ly) << 16);
}
// split two fp32 into packed fp16 hi / lo words
__device__ __forceinline__ void split2h(float x, float y, uint32_t& hi, uint32_t& lo) {
    __half hx = __float2half_rn(x), hy = __float2half_rn(y);
    __half lx = __float2half_rn(x - __half2float(hx));
    __half ly = __float2half_rn(y - __half2float(hy));
    hi = (uint32_t)__half_as_ushort(hx) | ((uint32_t)__half_as_ushort(hy) << 16);
    lo = (uint32_t)__half_as_ushort(lx) | ((uint32_t)__half_as_ushort(ly) << 16);
}

// ---------------- split kernels ----------------
__global__ void xsplit_kernel(const float* __restrict__ x,
                              __nv_bfloat16* __restrict__ h,
                              __nv_bfloat16* __restrict__ l, int n) {
    int i = blockIdx.x * blockDim.x + threadIdx.x;
    if (i < n) {
        float v = x[i];
        __nv_bfloat16 hh = __float2bfloat16(v);
        h[i] = hh;
        l[i] = __float2bfloat16(v - __bfloat162float(hh));
    }
}

// w [Kdim, Ndim] fp32 -> th/tl [Ndim, Kdim] bf16 (transposed split)
__global__ void wsplit_kernel(const float* __restrict__ w,
                              __nv_bfloat16* __restrict__ th,
                              __nv_bfloat16* __restrict__ tl,
                              int Kdim, int Ndim) {
    __shared__ float t[32][33];
    int n0 = blockIdx.x * 32, k0 = blockIdx.y * 32;
    int tx = threadIdx.x, ty = threadIdx.y;  // 32 x 8
#pragma unroll
    for (int i = 0; i < 32; i += 8)
        t[ty + i][tx] = w[(size_t)(k0 + ty + i) * Ndim + n0 + tx];
    __syncthreads();
#pragma unroll
    for (int i = 0; i < 32; i += 8) {
        float v = t[tx][ty + i];
        __nv_bfloat16 h = __float2bfloat16(v);
        __nv_bfloat16 l = __float2bfloat16(v - __bfloat162float(h));
        size_t o = (size_t)(n0 + ty + i) * Kdim + k0 + tx;
        th[o] = h;
        tl[o] = l;
    }
}

// ---------------- bf16x3 mma.sync GEMM ----------------
#define COMP_BYTES (128 * 80)
#define BUF_BYTES (4 * COMP_BYTES)
#define GEMM_SMEM (2 * BUF_BYTES)

__device__ __forceinline__ void load_chunk_async(
    const __nv_bfloat16* Ah, const __nv_bfloat16* Al,
    const __nv_bfloat16* Bh, const __nv_bfloat16* Bl,
    int K, int kc, uint32_t sbuf, int tid) {
    const __nv_bfloat16* gp[4] = {Ah, Al, Bh, Bl};
#pragma unroll
    for (int comp = 0; comp < 4; comp++) {
#pragma unroll
        for (int i = 0; i < 2; i++) {
            int id = tid + (i << 8);
            int r = id >> 2, c = id & 3;
            cp16(sbuf + comp * COMP_BYTES + r * 80 + c * 16,
                 gp[comp] + (size_t)r * K + kc + c * 8);
        }
    }
}

__global__ __launch_bounds__(256) void gemm_bf16x3_kernel(
    const __nv_bfloat16* __restrict__ Ah, const __nv_bfloat16* __restrict__ Al,
    const __nv_bfloat16* __restrict__ Bh, const __nv_bfloat16* __restrict__ Bl,
    float* __restrict__ C, int N, int K) {
    extern __shared__ char smem[];
    const uint32_t sb = smem_u32(smem);
    const int tid = threadIdx.x;
    const int wid = tid >> 5, lane = tid & 31;
    const int wm = wid >> 2, wn = wid & 3;
    const int g8 = lane >> 3, l8 = lane & 7;
    const int bm = blockIdx.y << 7, bn = blockIdx.x << 7;

    const __nv_bfloat16* pAh = Ah + (size_t)bm * K;
    const __nv_bfloat16* pAl = Al + (size_t)bm * K;
    const __nv_bfloat16* pBh = Bh + (size_t)bn * K;
    const __nv_bfloat16* pBl = Bl + (size_t)bn * K;

    float acc[4][4][4];
#pragma unroll
    for (int mt = 0; mt < 4; mt++)
#pragma unroll
        for (int nt = 0; nt < 4; nt++)
#pragma unroll
            for (int i = 0; i < 4; i++) acc[mt][nt][i] = 0.f;

    const int NC = K >> 5;
    load_chunk_async(pAh, pAl, pBh, pBl, K, 0, sb, tid);
    CP_COMMIT();

    const uint32_t aOff = (uint32_t)((wm * 64 + (g8 & 1) * 8 + l8) * 80 + (g8 >> 1) * 16);
    const uint32_t bOff = (uint32_t)((wn * 32 + (g8 >> 1) * 8 + l8) * 80 + (g8 & 1) * 16);

    for (int c = 0; c < NC; c++) {
        const uint32_t buf = sb + (uint32_t)(c & 1) * BUF_BYTES;
        if (c + 1 < NC) {
            load_chunk_async(pAh, pAl, pBh, pBl, K, (c + 1) << 5,
                             sb + (uint32_t)((c + 1) & 1) * BUF_BYTES, tid);
            CP_COMMIT();
            CP_WAIT1();
        } else {
            CP_WAIT0();
        }
        __syncthreads();

#pragma unroll
        for (int ks = 0; ks < 2; ks++) {
            const uint32_t kb = (uint32_t)(ks * 32);
            uint32_t ah[4][4], al[4][4], bh[2][4], bl[2][4];
#pragma unroll
            for (int mt = 0; mt < 4; mt++) {
                uint32_t ao = buf + aOff + (uint32_t)(mt * 16 * 80) + kb;
                ldm_x4(ah[mt], ao);
                ldm_x4(al[mt], ao + COMP_BYTES);
            }
#pragma unroll
            for (int ntp = 0; ntp < 2; ntp++) {
                uint32_t bo = buf + bOff + (uint32_t)(ntp * 16 * 80) + kb;
                ldm_x4(bh[ntp], bo + 2 * COMP_BYTES);
                ldm_x4(bl[ntp], bo + 3 * COMP_BYTES);
            }
#pragma unroll
            for (int mt = 0; mt < 4; mt++)
#pragma unroll
                for (int ntp = 0; ntp < 2; ntp++) {
                    mma16816(acc[mt][2 * ntp], ah[mt], bh[ntp]);
                    mma16816(acc[mt][2 * ntp], ah[mt], bl[ntp]);
                    mma16816(acc[mt][2 * ntp], al[mt], bh[ntp]);
                    mma16816(acc[mt][2 * ntp + 1], ah[mt], bh[ntp] + 2);
                    mma16816(acc[mt][2 * ntp + 1], ah[mt], bl[ntp] + 2);
                    mma16816(acc[mt][2 * ntp + 1], al[mt], bh[ntp] + 2);
                }
        }
        __syncthreads();
    }

#pragma unroll
    for (int mt = 0; mt < 4; mt++) {
        int row = bm + wm * 64 + mt * 16 + (lane >> 2);
#pragma unroll
        for (int nt = 0; nt < 4; nt++) {
            int col = bn + wn * 32 + nt * 8 + (lane & 3) * 2;
            *(float2*)(C + (size_t)row * N + col) =
                make_float2(acc[mt][nt][0], acc[mt][nt][1]);
            *(float2*)(C + (size_t)(row + 8) * N + col) =
                make_float2(acc[mt][nt][2], acc[mt][nt][3]);
        }
    }
}

// ---------------- RoPE on Q (in g_QKV), fp32 in-place ----------------
__global__ void rope_q_kernel(float* __restrict__ QKV,
                              const float* __restrict__ cosv,
                              const float* __restrict__ sinv) {
    const int qn = S * HQ * (HD / 2);
    int idx = blockIdx.x * blockDim.x + threadIdx.x;
    if (idx < qn) {
        int i = idx & 63;
        int h = (idx >> 6) & (HQ - 1);
        int s = idx >> 11;
        float c = cosv[(s << 6) + i];
        float sn = sinv[(s << 6) + i];
        float2* p = (float2*)(QKV + (size_t)s * QD + h * HD) + i;
        float2 v = *p;
        *p = make_float2(v.x * c - v.y * sn, v.x * sn + v.y * c);
    }
}

// ---------------- K rope + fp16 hi/lo split; V fp16 hi/lo split ----------------
__global__ void kvsplit_kernel(const float* __restrict__ QKV,
                               const float* __restrict__ cosv,
                               const float* __restrict__ sinv,
                               uint32_t* __restrict__ Kh, uint32_t* __restrict__ Kl,
                               uint32_t* __restrict__ Vh, uint32_t* __restrict__ Vl) {
    const int n = S * 512;  // pairs per tensor
    int idx = blockIdx.x * blockDim.x + threadIdx.x;
    if (idx < n) {  // K with rope
        int pc = idx & 511, s = idx >> 9;
        int i = pc & 63;
        float2 v = *(const float2*)(QKV + (size_t)s * QD + 4096 + pc * 2);
        float c = cosv[(s << 6) + i], sn = sinv[(s << 6) + i];
        uint32_t hw, lw;
        split2h(v.x * c - v.y * sn, v.x * sn + v.y * c, hw, lw);
        Kh[idx] = hw;
        Kl[idx] = lw;
    } else if (idx < 2 * n) {  // V
        int t = idx - n;
        int pc = t & 511, s = t >> 9;
        float2 v = *(const float2*)(QKV + (size_t)s * QD + 5120 + pc * 2);
        uint32_t hw, lw;
        split2h(v.x, v.y, hw, lw);
        Vh[t] = hw;
        Vl[t] = lw;
    }
}

// ---------------- Flash attention, fp16 mma, pre-split K/V + double buffer ----
#define QK_STR 272 /* bytes per 128-col f16 row */
#define P_STR 144
#define PS_STR 68
#define OFF_QH 0
#define OFF_QL 17408
#define OFF_KV 34816
#define KV_STAGE 69632
#define ST_KH 0
#define ST_KL 17408
#define ST_VH 34816
#define ST_VL 52224
#define OFF_PS 174080
#define OFF_PB 191488
#define OFF_PL 200704
#define OFF_FR 209920
#define OFF_IL 210176
#define ATTN2_SMEM 210432

__device__ __forceinline__ void issue_kv(const uint32_t* const* gp, int k0, int kvh,
                                         uint32_t stage, int tid) {
#pragma unroll
    for (int a = 0; a < 4; a++)
#pragma unroll
        for (int j = 0; j < 4; j++) {
            int id = tid + (j << 8);
            int r = id >> 4, c = id & 15;
            cp16(stage + a * 17408 + r * QK_STR + c * 16,
                 gp[a] + (size_t)(k0 + r) * 512 + kvh * 64 + c * 4);
        }
}

__global__ __launch_bounds__(256) void attn_mma_kernel(
    const float* __restrict__ Qg, const uint32_t* __restrict__ Khg,
    const uint32_t* __restrict__ Klg, const uint32_t* __restrict__ Vhg,
    const uint32_t* __restrict__ Vlg,
    __nv_bfloat16* __restrict__ Oh, __nv_bfloat16* __restrict__ Ol) {
    extern __shared__ char smb[];
    const uint32_t sb = smem_u32(smb);
    const int tid = threadIdx.x, wid = tid >> 5, lane = tid & 31;
    const int h = blockIdx.y, q0 = blockIdx.x * 64, kvh = h >> 2;
    const int wm = wid & 3, wn = wid >> 2;
    const int g8 = lane >> 3, l8 = lane & 7;
    const int row = tid >> 2, lr = tid & 3;
    const int r0 = wm * 16 + (lane >> 2);
    const float scale = 0.08838834764831845f;  // 1/sqrt(128)

    float* fRp = (float*)(smb + OFF_FR);
    float* iLp = (float*)(smb + OFF_IL);

    // load Q tile, fp16 hi/lo split
    for (int i = tid; i < 2048; i += 256) {
        int r = i >> 5, c4 = (i & 31) << 2;
        float4 q = *(const float4*)(Qg + (size_t)(q0 + r) * QD + h * HD + c4);
        uint32_t h0, l0, h1, l1;
        split2h(q.x, q.y, h0, l0);
        split2h(q.z, q.w, h1, l1);
        *(uint2*)(smb + OFF_QH + r * QK_STR + c4 * 2) = make_uint2(h0, h1);
        *(uint2*)(smb + OFF_QL + r * QK_STR + c4 * 2) = make_uint2(l0, l1);
    }

    float m_i = -CUDART_INF_F, l_i = 0.f;
    float oacc[8][4];
#pragma unroll
    for (int nt = 0; nt < 8; nt++)
#pragma unroll
        for (int i = 0; i < 4; i++) oacc[nt][i] = 0.f;

    const uint32_t aRow = (uint32_t)(wm * 16 + (g8 & 1) * 8 + l8);
    const uint32_t qhB = sb + OFF_QH + aRow * QK_STR;
    const uint32_t qlB = sb + OFF_QL + aRow * QK_STR;
    const uint32_t phB = sb + OFF_PB + aRow * P_STR;
    const uint32_t plB = sb + OFF_PL + aRow * P_STR;
    const uint32_t aColOfs = (uint32_t)((g8 >> 1) * 8) * 2;

    const uint32_t* gp[4] = {Khg, Klg, Vhg, Vlg};
    issue_kv(gp, 0, kvh, sb + OFF_KV, tid);
    CP_COMMIT();

    for (int k0 = 0; k0 <= q0; k0 += 64) {
        const int it = k0 >> 6;
        const uint32_t stage = sb + OFF_KV + (uint32_t)(it & 1) * KV_STAGE;
        __syncthreads();
        if (k0 + 64 <= q0) {
            issue_kv(gp, k0 + 64, kvh, sb + OFF_KV + (uint32_t)((it + 1) & 1) * KV_STAGE,
                     tid);
            CP_COMMIT();
            CP_WAIT1();
        } else {
            CP_WAIT0();
        }
        __syncthreads();

        // ---- scores: S = Q K^T (Qh*Kh + Qh*Kl + Ql*Kh) ----
        float sacc[4][4];
#pragma unroll
        for (int nt = 0; nt < 4; nt++)
#pragma unroll
            for (int i = 0; i < 4; i++) sacc[nt][i] = 0.f;

#pragma unroll
        for (int ks = 0; ks < 8; ks++) {
            uint32_t aH[4], aL[4];
            uint32_t co = (uint32_t)(ks * 16) * 2 + aColOfs;
            ldm_x4(aH, qhB + co);
            ldm_x4(aL, qlB + co);
#pragma unroll
            for (int ntp = 0; ntp < 2; ntp++) {
                uint32_t bH[4], bL[4];
                uint32_t nrow = (uint32_t)(wn * 32 + ntp * 16 + (g8 >> 1) * 8 + l8);
                uint32_t kof = (uint32_t)(ks * 16 + (g8 & 1) * 8) * 2;
                ldm_x4(bH, stage + ST_KH + nrow * QK_STR + kof);
                ldm_x4(bL, stage + ST_KL + nrow * QK_STR + kof);
                mma16816h(sacc[2 * ntp], aH, bH);
                mma16816h(sacc[2 * ntp], aH, bL);
                mma16816h(sacc[2 * ntp], aL, bH);
                mma16816h(sacc[2 * ntp + 1], aH, bH + 2);
                mma16816h(sacc[2 * ntp + 1], aH, bL + 2);
                mma16816h(sacc[2 * ntp + 1], aL, bH + 2);
            }
        }
        {
            float* Ps = (float*)(smb + OFF_PS);
            int qr0 = q0 + r0, qr1 = qr0 + 8;
#pragma unroll
            for (int nt = 0; nt < 4; nt++) {
                int c = wn * 32 + nt * 8 + (lane & 3) * 2;
                int kc = k0 + c;
                Ps[r0 * PS_STR + c] = (kc <= qr0) ? sacc[nt][0] * scale : -CUDART_INF_F;
                Ps[r0 * PS_STR + c + 1] =
                    (kc + 1 <= qr0) ? sacc[nt][1] * scale : -CUDART_INF_F;
                Ps[(r0 + 8) * PS_STR + c] =
                    (kc <= qr1) ? sacc[nt][2] * scale : -CUDART_INF_F;
                Ps[(r0 + 8) * PS_STR + c + 1] =
                    (kc + 1 <= qr1) ? sacc[nt][3] * scale : -CUDART_INF_F;
            }
        }
        __syncthreads();

        // ---- online softmax ----
        {
            const float* prow = (const float*)(smb + OFF_PS) + row * PS_STR + lr * 16;
            float pv[16];
            float rmax = -CUDART_INF_F;
#pragma unroll
            for (int j = 0; j < 16; j++) {
                pv[j] = prow[j];
                rmax = fmaxf(rmax, pv[j]);
            }
            rmax = fmaxf(rmax, __shfl_xor_sync(0xffffffff, rmax, 1));
            rmax = fmaxf(rmax, __shfl_xor_sync(0xffffffff, rmax, 2));
            float m_new = fmaxf(m_i, rmax);
            float rsum = 0.f;
#pragma unroll
            for (int j = 0; j < 16; j++) {
                pv[j] = __expf(pv[j] - m_new);
                rsum += pv[j];
            }
            rsum += __shfl_xor_sync(0xffffffff, rsum, 1);
            rsum += __shfl_xor_sync(0xffffffff, rsum, 2);
            float f = __expf(m_i - m_new);
            l_i = l_i * f + rsum;
            m_i = m_new;
            if (lr == 0) fRp[row] = f;
#pragma unroll
            for (int j = 0; j < 8; j++) {
                uint32_t hw, lw;
                split2h(pv[2 * j], pv[2 * j + 1], hw, lw);
                int po = row * P_STR + (lr * 16 + 2 * j) * 2;
                *(uint32_t*)(smb + OFF_PB + po) = hw;
                *(uint32_t*)(smb + OFF_PL + po) = lw;
            }
        }
        __syncthreads();

        // ---- PV: O = (Ph+Pl)*(Vh+Vl) less lo*lo, online rescale ----
        {
            float f0 = fRp[r0], f1 = fRp[r0 + 8];
#pragma unroll
            for (int nt = 0; nt < 8; nt++) {
                oacc[nt][0] *= f0;
                oacc[nt][1] *= f0;
                oacc[nt][2] *= f1;
                oacc[nt][3] *= f1;
            }
#pragma unroll
            for (int ks = 0; ks < 4; ks++) {
                uint32_t aP[4], aPl[4];
                uint32_t po = (uint32_t)(ks * 16) * 2 + ((uint32_t)((g8 >> 1) * 8) * 2);
                ldm_x4(aP, phB + po);
                ldm_x4(aPl, plB + po);
                uint32_t krow = (uint32_t)(ks * 16 + (g8 & 1) * 8 + l8);
#pragma unroll
                for (int ntp = 0; ntp < 4; ntp++) {
                    uint32_t bH[4], bL[4];
                    uint32_t ncol = (uint32_t)(wn * 64 + ntp * 16 + (g8 >> 1) * 8);
                    ldm_x4_t(bH, stage + ST_VH + krow * QK_STR + ncol * 2);
                    ldm_x4_t(bL, stage + ST_VL + krow * QK_STR + ncol * 2);
                    mma16816h(oacc[2 * ntp], aP, bH);
                    mma16816h(oacc[2 * ntp], aP, bL);
                    mma16816h(oacc[2 * ntp], aPl, bH);
                    mma16816h(oacc[2 * ntp + 1], aP, bH + 2);
                    mma16816h(oacc[2 * ntp + 1], aP, bL + 2);
                    mma16816h(oacc[2 * ntp + 1], aPl, bH + 2);
                }
            }
        }
    }

    if (lr == 0) iLp[row] = 1.f / l_i;
    __syncthreads();

    // finalize: scale by 1/l, write bf16 hi/lo (feeds wo GEMM)
    {
        float i0 = iLp[r0], i1 = iLp[r0 + 8];
#pragma unroll
        for (int nt = 0; nt < 8; nt++) {
            int col = h * HD + wn * 64 + nt * 8 + (lane & 3) * 2;
            size_t o0 = (size_t)(q0 + r0) * D + col;
            size_t o1 = (size_t)(q0 + r0 + 8) * D + col;
            uint32_t hh, ll;
            split2(oacc[nt][0] * i0, oacc[nt][1] * i0, hh, ll);
            *(uint32_t*)(Oh + o0) = hh;
            *(uint32_t*)(Ol + o0) = ll;
            split2(oacc[nt][2] * i1, oacc[nt][3] * i1, hh, ll);
            *(uint32_t*)(Oh + o1) = hh;
            *(uint32_t*)(Ol + o1) = ll;
        }
    }
}

// ---------------- launch ----------------
extern "C" void kernel_launch(void* const* d_in, const int* in_sizes, int n_in,
                              void* d_out, int out_size) {
    const float* x = (const float*)d_in[0];
    const float* wq = (const float*)d_in[1];
    const float* wk = (const float*)d_in[2];
    const float* wv = (const float*)d_in[3];
    const float* wo = (const float*)d_in[4];
    const float* cosv = (const float*)d_in[5];
    const float* sinv = (const float*)d_in[6];
    float* out = (float*)d_out;

    float* pQKV;
    cudaGetSymbolAddress((void**)&pQKV, g_QKV);
    __nv_bfloat16 *pXh, *pXl, *pWh, *pWl, *pWoh, *pWol;
    cudaGetSymbolAddress((void**)&pXh, g_Xh);
    cudaGetSymbolAddress((void**)&pXl, g_Xl);
    cudaGetSymbolAddress((void**)&pWh, g_Wh);
    cudaGetSymbolAddress((void**)&pWl, g_Wl);
    cudaGetSymbolAddress((void**)&pWoh, g_Woh);
    cudaGetSymbolAddress((void**)&pWol, g_Wol);
    uint32_t *pKh, *pKl, *pVh, *pVl;
    cudaGetSymbolAddress((void**)&pKh, g_Kh16);
    cudaGetSymbolAddress((void**)&pKl, g_Kl16);
    cudaGetSymbolAddress((void**)&pVh, g_Vh16);
    cudaGetSymbolAddress((void**)&pVl, g_Vl16);

    cudaFuncSetAttribute(gemm_bf16x3_kernel,
                         cudaFuncAttributeMaxDynamicSharedMemorySize, GEMM_SMEM);
    cudaFuncSetAttribute(attn_mma_kernel,
                         cudaFuncAttributeMaxDynamicSharedMemorySize, ATTN2_SMEM);

    // x split + transposed weight splits ([Wq;Wk;Wv] combined, Wo separate)
    {
        int n = S * D;
        xsplit_kernel<<<(n + 255) / 256, 256>>>(x, pXh, pXl, n);
    }
    wsplit_kernel<<<dim3(D / 32, D / 32), dim3(32, 8)>>>(wq, pWh, pWl, D, D);
    wsplit_kernel<<<dim3(KV_W / 32, D / 32), dim3(32, 8)>>>(
        wk, pWh + (size_t)4096 * D, pWl + (size_t)4096 * D, D, KV_W);
    wsplit_kernel<<<dim3(KV_W / 32, D / 32), dim3(32, 8)>>>(
        wv, pWh + (size_t)5120 * D, pWl + (size_t)5120 * D, D, KV_W);
    wsplit_kernel<<<dim3(D / 32, D / 32), dim3(32, 8)>>>(wo, pWoh, pWol, D, D);

    // combined QKV projection (one full-chip GEMM, N=6144)
    gemm_bf16x3_kernel<<<dim3(QD / 128, S / 128), 256, GEMM_SMEM>>>(
        pXh, pXl, pWh, pWl, pQKV, QD, D);

    // RoPE on Q; K rope + fp16 pre-split; V fp16 pre-split
    {
        int qn = S * HQ * (HD / 2);
        rope_q_kernel<<<(qn + 255) / 256, 256>>>(pQKV, cosv, sinv);
        int kvn = 2 * S * 512;
        kvsplit_kernel<<<(kvn + 255) / 256, 256>>>(pQKV, cosv, sinv, pKh, pKl, pVh,
                                                   pVl);
    }

    // attention (fp16 mma, double-buffered pre-split K/V; writes bf16 hi/lo)
    attn_mma_kernel<<<dim3(S / 64, HQ), 256, ATTN2_SMEM>>>(pQKV, pKh, pKl, pVh, pVl,
                                                           pXh, pXl);

    // output projection
    gemm_bf16x3_kernel<<<dim3(D / 128, S / 128), 256, GEMM_SMEM>>>(
        pXh, pXl, pWoh, pWol, out, D, D);
}

// round 15
// speedup vs baseline: 6.2769x; 1.5089x over previous
#include <cuda_runtime.h>
#include <cuda_bf16.h>
#include <cuda_fp16.h>
#include <math_constants.h>
#include <cstdint>
#include <cstddef>

#define S 2048
#define D 4096
#define HQ 32
#define HKV 8
#define HD 128
#define KV_W (HKV * HD) /* 1024 */
#define QD 6144         /* combined QKV output width */

// ---------------- scratch (no allocations allowed) ----------------
__device__ float g_QKV[(size_t)S * QD];  // Q | K | V fp32 (50 MB)

// fp16 planes: activations hi+lo (x, then attn out); weights single fp16
__device__ __half g_Xh[(size_t)S * D], g_Xl[(size_t)S * D];
__device__ __half g_Wh[(size_t)QD * D];   // [Wq;Wk;Wv]^T single fp16
__device__ __half g_Woh[(size_t)D * D];   // Wo^T single fp16

// pre-split fp16 K/V (2 fp16 per word)
__device__ uint32_t g_Kh16[(size_t)S * 512], g_Kl16[(size_t)S * 512];
__device__ uint32_t g_Vh16[(size_t)S * 512], g_Vl16[(size_t)S * 512];

// ---------------- mma.sync / cp.async / ldmatrix helpers ----------------
__device__ __forceinline__ uint32_t smem_u32(const void* p) {
    uint32_t a;
    asm("{ .reg .u64 t; cvta.to.shared.u64 t, %1; cvt.u32.u64 %0, t; }"
        : "=r"(a) : "l"(p));
    return a;
}
// fp16 mma (GEMMs + attention)
__device__ __forceinline__ void mma16816h(float* d, const uint32_t* a,
                                          const uint32_t* b) {
    asm volatile(
        "mma.sync.aligned.m16n8k16.row.col.f32.f16.f16.f32 "
        "{%0,%1,%2,%3}, {%4,%5,%6,%7}, {%8,%9}, {%0,%1,%2,%3};"
        : "+f"(d[0]), "+f"(d[1]), "+f"(d[2]), "+f"(d[3])
        : "r"(a[0]), "r"(a[1]), "r"(a[2]), "r"(a[3]), "r"(b[0]), "r"(b[1]));
}
__device__ __forceinline__ void cp16(uint32_t sdst, const void* gsrc) {
    asm volatile("cp.async.cg.shared.global [%0], [%1], 16;"
                 :: "r"(sdst), "l"(gsrc) : "memory");
}
#define CP_COMMIT() asm volatile("cp.async.commit_group;" ::: "memory")
#define CP_WAIT1() asm volatile("cp.async.wait_group 1;" ::: "memory")
#define CP_WAIT0() asm volatile("cp.async.wait_group 0;" ::: "memory")

__device__ __forceinline__ void ldm_x4(uint32_t* r, uint32_t a) {
    asm volatile("ldmatrix.sync.aligned.m8n8.x4.shared.b16 {%0,%1,%2,%3}, [%4];"
                 : "=r"(r[0]), "=r"(r[1]), "=r"(r[2]), "=r"(r[3]) : "r"(a));
}
__device__ __forceinline__ void ldm_x4_t(uint32_t* r, uint32_t a) {
    asm volatile("ldmatrix.sync.aligned.m8n8.x4.trans.shared.b16 {%0,%1,%2,%3}, [%4];"
                 : "=r"(r[0]), "=r"(r[1]), "=r"(r[2]), "=r"(r[3]) : "r"(a));
}
// fp32 -> packed fp16 hi/lo
__device__ __forceinline__ void split2h(float x, float y, uint32_t& hi, uint32_t& lo) {
    __half hx = __float2half_rn(x), hy = __float2half_rn(y);
    __half lx = __float2half_rn(x - __half2float(hx));
    __half ly = __float2half_rn(y - __half2float(hy));
    hi = (uint32_t)__half_as_ushort(hx) | ((uint32_t)__half_as_ushort(hy) << 16);
    lo = (uint32_t)__half_as_ushort(lx) | ((uint32_t)__half_as_ushort(ly) << 16);
}

// ---------------- split kernels ----------------
// activations: fp16 hi/lo planes
__global__ void xsplit_kernel(const float* __restrict__ x,
                              __half* __restrict__ h, __half* __restrict__ l,
                              int n) {
    int i = blockIdx.x * blockDim.x + threadIdx.x;
    if (i < n) {
        float v = x[i];
        __half hh = __float2half_rn(v);
        h[i] = hh;
        l[i] = __float2half_rn(v - __half2float(hh));
    }
}

// w [Kdim, Ndim] fp32 -> th [Ndim, Kdim] single fp16 (transposed)
__global__ void wsplit_kernel(const float* __restrict__ w,
                              __half* __restrict__ th, int Kdim, int Ndim) {
    __shared__ float t[32][33];
    int n0 = blockIdx.x * 32, k0 = blockIdx.y * 32;
    int tx = threadIdx.x, ty = threadIdx.y;  // 32 x 8
#pragma unroll
    for (int i = 0; i < 32; i += 8)
        t[ty + i][tx] = w[(size_t)(k0 + ty + i) * Ndim + n0 + tx];
    __syncthreads();
#pragma unroll
    for (int i = 0; i < 32; i += 8)
        th[(size_t)(n0 + ty + i) * Kdim + k0 + tx] = __float2half_rn(t[tx][ty + i]);
}

// ---------------- fp16 2-term mma.sync GEMM ----------------
// C = (Ah + Al) . Bh  (A fp16 hi/lo planes, B single fp16, fp32 accum)
#define COMP_BYTES (128 * 80)
#define BUF_BYTES (3 * COMP_BYTES)
#define GEMM_SMEM (2 * BUF_BYTES) /* 61440 */

__device__ __forceinline__ void load_chunk_async(
    const __half* Ah, const __half* Al, const __half* Bh,
    int K, int kc, uint32_t sbuf, int tid) {
    const __half* gp[3] = {Ah, Al, Bh};
#pragma unroll
    for (int comp = 0; comp < 3; comp++) {
#pragma unroll
        for (int i = 0; i < 2; i++) {
            int id = tid + (i << 8);
            int r = id >> 2, c = id & 3;
            cp16(sbuf + comp * COMP_BYTES + r * 80 + c * 16,
                 gp[comp] + (size_t)r * K + kc + c * 8);
        }
    }
}

__global__ __launch_bounds__(256) void gemm_f16x2_kernel(
    const __half* __restrict__ Ah, const __half* __restrict__ Al,
    const __half* __restrict__ Bh, float* __restrict__ C, int N, int K) {
    extern __shared__ char smem[];
    const uint32_t sb = smem_u32(smem);
    const int tid = threadIdx.x;
    const int wid = tid >> 5, lane = tid & 31;
    const int wm = wid >> 2, wn = wid & 3;
    const int g8 = lane >> 3, l8 = lane & 7;
    const int bm = blockIdx.y << 7, bn = blockIdx.x << 7;

    const __half* pAh = Ah + (size_t)bm * K;
    const __half* pAl = Al + (size_t)bm * K;
    const __half* pBh = Bh + (size_t)bn * K;

    float acc[4][4][4];
#pragma unroll
    for (int mt = 0; mt < 4; mt++)
#pragma unroll
        for (int nt = 0; nt < 4; nt++)
#pragma unroll
            for (int i = 0; i < 4; i++) acc[mt][nt][i] = 0.f;

    const int NC = K >> 5;
    load_chunk_async(pAh, pAl, pBh, K, 0, sb, tid);
    CP_COMMIT();

    const uint32_t aOff = (uint32_t)((wm * 64 + (g8 & 1) * 8 + l8) * 80 + (g8 >> 1) * 16);
    const uint32_t bOff = (uint32_t)((wn * 32 + (g8 >> 1) * 8 + l8) * 80 + (g8 & 1) * 16);

    for (int c = 0; c < NC; c++) {
        const uint32_t buf = sb + (uint32_t)(c & 1) * BUF_BYTES;
        if (c + 1 < NC) {
            load_chunk_async(pAh, pAl, pBh, K, (c + 1) << 5,
                             sb + (uint32_t)((c + 1) & 1) * BUF_BYTES, tid);
            CP_COMMIT();
            CP_WAIT1();
        } else {
            CP_WAIT0();
        }
        __syncthreads();

#pragma unroll
        for (int ks = 0; ks < 2; ks++) {
            const uint32_t kb = (uint32_t)(ks * 32);
            uint32_t ah[4][4], al[4][4], bh[2][4];
#pragma unroll
            for (int mt = 0; mt < 4; mt++) {
                uint32_t ao = buf + aOff + (uint32_t)(mt * 16 * 80) + kb;
                ldm_x4(ah[mt], ao);
                ldm_x4(al[mt], ao + COMP_BYTES);
            }
#pragma unroll
            for (int ntp = 0; ntp < 2; ntp++) {
                uint32_t bo = buf + bOff + (uint32_t)(ntp * 16 * 80) + kb;
                ldm_x4(bh[ntp], bo + 2 * COMP_BYTES);
            }
#pragma unroll
            for (int mt = 0; mt < 4; mt++)
#pragma unroll
                for (int ntp = 0; ntp < 2; ntp++) {
                    mma16816h(acc[mt][2 * ntp], ah[mt], bh[ntp]);
                    mma16816h(acc[mt][2 * ntp], al[mt], bh[ntp]);
                    mma16816h(acc[mt][2 * ntp + 1], ah[mt], bh[ntp] + 2);
                    mma16816h(acc[mt][2 * ntp + 1], al[mt], bh[ntp] + 2);
                }
        }
        __syncthreads();
    }

#pragma unroll
    for (int mt = 0; mt < 4; mt++) {
        int row = bm + wm * 64 + mt * 16 + (lane >> 2);
#pragma unroll
        for (int nt = 0; nt < 4; nt++) {
            int col = bn + wn * 32 + nt * 8 + (lane & 3) * 2;
            *(float2*)(C + (size_t)row * N + col) =
                make_float2(acc[mt][nt][0], acc[mt][nt][1]);
            *(float2*)(C + (size_t)(row + 8) * N + col) =
                make_float2(acc[mt][nt][2], acc[mt][nt][3]);
        }
    }
}

// ---------------- RoPE on Q (in g_QKV), fp32 in-place ----------------
__global__ void rope_q_kernel(float* __restrict__ QKV,
                              const float* __restrict__ cosv,
                              const float* __restrict__ sinv) {
    const int qn = S * HQ * (HD / 2);
    int idx = blockIdx.x * blockDim.x + threadIdx.x;
    if (idx < qn) {
        int i = idx & 63;
        int h = (idx >> 6) & (HQ - 1);
        int s = idx >> 11;
        float c = cosv[(s << 6) + i];
        float sn = sinv[(s << 6) + i];
        float2* p = (float2*)(QKV + (size_t)s * QD + h * HD) + i;
        float2 v = *p;
        *p = make_float2(v.x * c - v.y * sn, v.x * sn + v.y * c);
    }
}

// ---------------- K rope + fp16 hi/lo split; V fp16 hi/lo split ----------------
__global__ void kvsplit_kernel(const float* __restrict__ QKV,
                               const float* __restrict__ cosv,
                               const float* __restrict__ sinv,
                               uint32_t* __restrict__ Kh, uint32_t* __restrict__ Kl,
                               uint32_t* __restrict__ Vh, uint32_t* __restrict__ Vl) {
    const int n = S * 512;  // pairs per tensor
    int idx = blockIdx.x * blockDim.x + threadIdx.x;
    if (idx < n) {  // K with rope
        int pc = idx & 511, s = idx >> 9;
        int i = pc & 63;
        float2 v = *(const float2*)(QKV + (size_t)s * QD + 4096 + pc * 2);
        float c = cosv[(s << 6) + i], sn = sinv[(s << 6) + i];
        uint32_t hw, lw;
        split2h(v.x * c - v.y * sn, v.x * sn + v.y * c, hw, lw);
        Kh[idx] = hw;
        Kl[idx] = lw;
    } else if (idx < 2 * n) {  // V
        int t = idx - n;
        int pc = t & 511, s = t >> 9;
        float2 v = *(const float2*)(QKV + (size_t)s * QD + 5120 + pc * 2);
        uint32_t hw, lw;
        split2h(v.x, v.y, hw, lw);
        Vh[t] = hw;
        Vl[t] = lw;
    }
}

// ---------------- Flash attention, fp16 mma, pre-split K/V + double buffer ----
#define QK_STR 272 /* bytes per 128-col f16 row */
#define P_STR 144
#define PS_STR 68
#define OFF_QH 0
#define OFF_QL 17408
#define OFF_KV 34816
#define KV_STAGE 69632
#define ST_KH 0
#define ST_KL 17408
#define ST_VH 34816
#define ST_VL 52224
#define OFF_PS 174080
#define OFF_PB 191488
#define OFF_PL 200704
#define OFF_FR 209920
#define OFF_IL 210176
#define ATTN2_SMEM 210432

__device__ __forceinline__ void issue_kv(const uint32_t* const* gp, int k0, int kvh,
                                         uint32_t stage, int tid) {
#pragma unroll
    for (int a = 0; a < 4; a++)
#pragma unroll
        for (int j = 0; j < 4; j++) {
            int id = tid + (j << 8);
            int r = id >> 4, c = id & 15;
            cp16(stage + a * 17408 + r * QK_STR + c * 16,
                 gp[a] + (size_t)(k0 + r) * 512 + kvh * 64 + c * 4);
        }
}

__global__ __launch_bounds__(256) void attn_mma_kernel(
    const float* __restrict__ Qg, const uint32_t* __restrict__ Khg,
    const uint32_t* __restrict__ Klg, const uint32_t* __restrict__ Vhg,
    const uint32_t* __restrict__ Vlg,
    __half* __restrict__ Oh, __half* __restrict__ Ol) {
    extern __shared__ char smb[];
    const uint32_t sb = smem_u32(smb);
    const int tid = threadIdx.x, wid = tid >> 5, lane = tid & 31;
    const int h = blockIdx.y, q0 = blockIdx.x * 64, kvh = h >> 2;
    const int wm = wid & 3, wn = wid >> 2;
    const int g8 = lane >> 3, l8 = lane & 7;
    const int row = tid >> 2, lr = tid & 3;
    const int r0 = wm * 16 + (lane >> 2);
    const float scale = 0.08838834764831845f;  // 1/sqrt(128)

    float* fRp = (float*)(smb + OFF_FR);
    float* iLp = (float*)(smb + OFF_IL);

    // load Q tile, fp16 hi/lo split
    for (int i = tid; i < 2048; i += 256) {
        int r = i >> 5, c4 = (i & 31) << 2;
        float4 q = *(const float4*)(Qg + (size_t)(q0 + r) * QD + h * HD + c4);
        uint32_t h0, l0, h1, l1;
        split2h(q.x, q.y, h0, l0);
        split2h(q.z, q.w, h1, l1);
        *(uint2*)(smb + OFF_QH + r * QK_STR + c4 * 2) = make_uint2(h0, h1);
        *(uint2*)(smb + OFF_QL + r * QK_STR + c4 * 2) = make_uint2(l0, l1);
    }

    float m_i = -CUDART_INF_F, l_i = 0.f;
    float oacc[8][4];
#pragma unroll
    for (int nt = 0; nt < 8; nt++)
#pragma unroll
        for (int i = 0; i < 4; i++) oacc[nt][i] = 0.f;

    const uint32_t aRow = (uint32_t)(wm * 16 + (g8 & 1) * 8 + l8);
    const uint32_t qhB = sb + OFF_QH + aRow * QK_STR;
    const uint32_t qlB = sb + OFF_QL + aRow * QK_STR;
    const uint32_t phB = sb + OFF_PB + aRow * P_STR;
    const uint32_t plB = sb + OFF_PL + aRow * P_STR;
    const uint32_t aColOfs = (uint32_t)((g8 >> 1) * 8) * 2;

    const uint32_t* gp[4] = {Khg, Klg, Vhg, Vlg};
    issue_kv(gp, 0, kvh, sb + OFF_KV, tid);
    CP_COMMIT();

    for (int k0 = 0; k0 <= q0; k0 += 64) {
        const int it = k0 >> 6;
        const uint32_t stage = sb + OFF_KV + (uint32_t)(it & 1) * KV_STAGE;
        __syncthreads();
        if (k0 + 64 <= q0) {
            issue_kv(gp, k0 + 64, kvh, sb + OFF_KV + (uint32_t)((it + 1) & 1) * KV_STAGE,
                     tid);
            CP_COMMIT();
            CP_WAIT1();
        } else {
            CP_WAIT0();
        }
        __syncthreads();

        // ---- scores: S = Q K^T (Qh*Kh + Qh*Kl + Ql*Kh) ----
        float sacc[4][4];
#pragma unroll
        for (int nt = 0; nt < 4; nt++)
#pragma unroll
            for (int i = 0; i < 4; i++) sacc[nt][i] = 0.f;

#pragma unroll
        for (int ks = 0; ks < 8; ks++) {
            uint32_t aH[4], aL[4];
            uint32_t co = (uint32_t)(ks * 16) * 2 + aColOfs;
            ldm_x4(aH, qhB + co);
            ldm_x4(aL, qlB + co);
#pragma unroll
            for (int ntp = 0; ntp < 2; ntp++) {
                uint32_t bH[4], bL[4];
                uint32_t nrow = (uint32_t)(wn * 32 + ntp * 16 + (g8 >> 1) * 8 + l8);
                uint32_t kof = (uint32_t)(ks * 16 + (g8 & 1) * 8) * 2;
                ldm_x4(bH, stage + ST_KH + nrow * QK_STR + kof);
                ldm_x4(bL, stage + ST_KL + nrow * QK_STR + kof);
                mma16816h(sacc[2 * ntp], aH, bH);
                mma16816h(sacc[2 * ntp], aH, bL);
                mma16816h(sacc[2 * ntp], aL, bH);
                mma16816h(sacc[2 * ntp + 1], aH, bH + 2);
                mma16816h(sacc[2 * ntp + 1], aH, bL + 2);
                mma16816h(sacc[2 * ntp + 1], aL, bH + 2);
            }
        }
        {
            float* Ps = (float*)(smb + OFF_PS);
            int qr0 = q0 + r0, qr1 = qr0 + 8;
#pragma unroll
            for (int nt = 0; nt < 4; nt++) {
                int c = wn * 32 + nt * 8 + (lane & 3) * 2;
                int kc = k0 + c;
                Ps[r0 * PS_STR + c] = (kc <= qr0) ? sacc[nt][0] * scale : -CUDART_INF_F;
                Ps[r0 * PS_STR + c + 1] =
                    (kc + 1 <= qr0) ? sacc[nt][1] * scale : -CUDART_INF_F;
                Ps[(r0 + 8) * PS_STR + c] =
                    (kc <= qr1) ? sacc[nt][2] * scale : -CUDART_INF_F;
                Ps[(r0 + 8) * PS_STR + c + 1] =
                    (kc + 1 <= qr1) ? sacc[nt][3] * scale : -CUDART_INF_F;
            }
        }
        __syncthreads();

        // ---- online softmax ----
        {
            const float* prow = (const float*)(smb + OFF_PS) + row * PS_STR + lr * 16;
            float pv[16];
            float rmax = -CUDART_INF_F;
#pragma unroll
            for (int j = 0; j < 16; j++) {
                pv[j] = prow[j];
                rmax = fmaxf(rmax, pv[j]);
            }
            rmax = fmaxf(rmax, __shfl_xor_sync(0xffffffff, rmax, 1));
            rmax = fmaxf(rmax, __shfl_xor_sync(0xffffffff, rmax, 2));
            float m_new = fmaxf(m_i, rmax);
            float rsum = 0.f;
#pragma unroll
            for (int j = 0; j < 16; j++) {
                pv[j] = __expf(pv[j] - m_new);
                rsum += pv[j];
            }
            rsum += __shfl_xor_sync(0xffffffff, rsum, 1);
            rsum += __shfl_xor_sync(0xffffffff, rsum, 2);
            float f = __expf(m_i - m_new);
            l_i = l_i * f + rsum;
            m_i = m_new;
            if (lr == 0) fRp[row] = f;
#pragma unroll
            for (int j = 0; j < 8; j++) {
                uint32_t hw, lw;
                split2h(pv[2 * j], pv[2 * j + 1], hw, lw);
                int po = row * P_STR + (lr * 16 + 2 * j) * 2;
                *(uint32_t*)(smb + OFF_PB + po) = hw;
                *(uint32_t*)(smb + OFF_PL + po) = lw;
            }
        }
        __syncthreads();

        // ---- PV: O = (Ph+Pl)*(Vh+Vl) less lo*lo, online rescale ----
        {
            float f0 = fRp[r0], f1 = fRp[r0 + 8];
#pragma unroll
            for (int nt = 0; nt < 8; nt++) {
                oacc[nt][0] *= f0;
                oacc[nt][1] *= f0;
                oacc[nt][2] *= f1;
                oacc[nt][3] *= f1;
            }
#pragma unroll
            for (int ks = 0; ks < 4; ks++) {
                uint32_t aP[4], aPl[4];
                uint32_t po = (uint32_t)(ks * 16) * 2 + ((uint32_t)((g8 >> 1) * 8) * 2);
                ldm_x4(aP, phB + po);
                ldm_x4(aPl, plB + po);
                uint32_t krow = (uint32_t)(ks * 16 + (g8 & 1) * 8 + l8);
#pragma unroll
                for (int ntp = 0; ntp < 4; ntp++) {
                    uint32_t bH[4], bL[4];
                    uint32_t ncol = (uint32_t)(wn * 64 + ntp * 16 + (g8 >> 1) * 8);
                    ldm_x4_t(bH, stage + ST_VH + krow * QK_STR + ncol * 2);
                    ldm_x4_t(bL, stage + ST_VL + krow * QK_STR + ncol * 2);
                    mma16816h(oacc[2 * ntp], aP, bH);
                    mma16816h(oacc[2 * ntp], aP, bL);
                    mma16816h(oacc[2 * ntp], aPl, bH);
                    mma16816h(oacc[2 * ntp + 1], aP, bH + 2);
                    mma16816h(oacc[2 * ntp + 1], aP, bL + 2);
                    mma16816h(oacc[2 * ntp + 1], aPl, bH + 2);
                }
            }
        }
    }

    if (lr == 0) iLp[row] = 1.f / l_i;
    __syncthreads();

    // finalize: scale by 1/l, write fp16 hi/lo (feeds wo GEMM A-side)
    {
        float i0 = iLp[r0], i1 = iLp[r0 + 8];
#pragma unroll
        for (int nt = 0; nt < 8; nt++) {
            int col = h * HD + wn * 64 + nt * 8 + (lane & 3) * 2;
            size_t o0 = (size_t)(q0 + r0) * D + col;
            size_t o1 = (size_t)(q0 + r0 + 8) * D + col;
            uint32_t hh, ll;
            split2h(oacc[nt][0] * i0, oacc[nt][1] * i0, hh, ll);
            *(uint32_t*)(Oh + o0) = hh;
            *(uint32_t*)(Ol + o0) = ll;
            split2h(oacc[nt][2] * i1, oacc[nt][3] * i1, hh, ll);
            *(uint32_t*)(Oh + o1) = hh;
            *(uint32_t*)(Ol + o1) = ll;
        }
    }
}

// ---------------- launch ----------------
extern "C" void kernel_launch(void* const* d_in, const int* in_sizes, int n_in,
                              void* d_out, int out_size) {
    const float* x = (const float*)d_in[0];
    const float* wq = (const float*)d_in[1];
    const float* wk = (const float*)d_in[2];
    const float* wv = (const float*)d_in[3];
    const float* wo = (const float*)d_in[4];
    const float* cosv = (const float*)d_in[5];
    const float* sinv = (const float*)d_in[6];
    float* out = (float*)d_out;

    float* pQKV;
    cudaGetSymbolAddress((void**)&pQKV, g_QKV);
    __half *pXh, *pXl, *pWh, *pWoh;
    cudaGetSymbolAddress((void**)&pXh, g_Xh);
    cudaGetSymbolAddress((void**)&pXl, g_Xl);
    cudaGetSymbolAddress((void**)&pWh, g_Wh);
    cudaGetSymbolAddress((void**)&pWoh, g_Woh);
    uint32_t *pKh, *pKl, *pVh, *pVl;
    cudaGetSymbolAddress((void**)&pKh, g_Kh16);
    cudaGetSymbolAddress((void**)&pKl, g_Kl16);
    cudaGetSymbolAddress((void**)&pVh, g_Vh16);
    cudaGetSymbolAddress((void**)&pVl, g_Vl16);

    cudaFuncSetAttribute(gemm_f16x2_kernel,
                         cudaFuncAttributeMaxDynamicSharedMemorySize, GEMM_SMEM);
    cudaFuncSetAttribute(attn_mma_kernel,
                         cudaFuncAttributeMaxDynamicSharedMemorySize, ATTN2_SMEM);

    // x split (fp16 hi/lo) + transposed single-fp16 weights
    {
        int n = S * D;
        xsplit_kernel<<<(n + 255) / 256, 256>>>(x, pXh, pXl, n);
    }
    wsplit_kernel<<<dim3(D / 32, D / 32), dim3(32, 8)>>>(wq, pWh, D, D);
    wsplit_kernel<<<dim3(KV_W / 32, D / 32), dim3(32, 8)>>>(
        wk, pWh + (size_t)4096 * D, D, KV_W);
    wsplit_kernel<<<dim3(KV_W / 32, D / 32), dim3(32, 8)>>>(
        wv, pWh + (size_t)5120 * D, D, KV_W);
    wsplit_kernel<<<dim3(D / 32, D / 32), dim3(32, 8)>>>(wo, pWoh, D, D);

    // combined QKV projection (fp16 2-term GEMM, N=6144)
    gemm_f16x2_kernel<<<dim3(QD / 128, S / 128), 256, GEMM_SMEM>>>(
        pXh, pXl, pWh, pQKV, QD, D);

    // RoPE on Q; K rope + fp16 pre-split; V fp16 pre-split
    {
        int qn = S * HQ * (HD / 2);
        rope_q_kernel<<<(qn + 255) / 256, 256>>>(pQKV, cosv, sinv);
        int kvn = 2 * S * 512;
        kvsplit_kernel<<<(kvn + 255) / 256, 256>>>(pQKV, cosv, sinv, pKh, pKl, pVh,
                                                   pVl);
    }

    // attention (fp16 mma, compensated; writes fp16 hi/lo into X planes)
    attn_mma_kernel<<<dim3(S / 64, HQ), 256, ATTN2_SMEM>>>(pQKV, pKh, pKl, pVh, pVl,
                                                           pXh, pXl);

    // output projection (fp16 2-term GEMM)
    gemm_f16x2_kernel<<<dim3(D / 128, S / 128), 256, GEMM_SMEM>>>(
        pXh, pXl, pWoh, out, D, D);
}

// round 16
// speedup vs baseline: 6.6883x; 1.0655x over previous
#include <cuda_runtime.h>
#include <cuda_bf16.h>
#include <cuda_fp16.h>
#include <math_constants.h>
#include <cstdint>
#include <cstddef>

#define S 2048
#define D 4096
#define HQ 32
#define HKV 8
#define HD 128
#define KV_W (HKV * HD) /* 1024 */
#define QD 6144         /* combined QKV output width */

// ---------------- scratch (no allocations allowed) ----------------
__device__ float g_QKV[(size_t)S * QD];  // Q | K | V fp32 (50 MB)

// fp16 planes: activations hi+lo (x, then attn out); weights single fp16
__device__ __half g_Xh[(size_t)S * D], g_Xl[(size_t)S * D];
__device__ __half g_Wh[(size_t)QD * D];   // [Wq;Wk;Wv]^T single fp16
__device__ __half g_Woh[(size_t)D * D];   // Wo^T single fp16

// pre-split fp16 K (hi/lo) and V (single) for attention
__device__ uint32_t g_Kh16[(size_t)S * 512], g_Kl16[(size_t)S * 512];
__device__ uint32_t g_Vh16[(size_t)S * 512];

// ---------------- mma.sync / cp.async / ldmatrix helpers ----------------
__device__ __forceinline__ uint32_t smem_u32(const void* p) {
    uint32_t a;
    asm("{ .reg .u64 t; cvta.to.shared.u64 t, %1; cvt.u32.u64 %0, t; }"
        : "=r"(a) : "l"(p));
    return a;
}
// fp16 mma (GEMMs + attention)
__device__ __forceinline__ void mma16816h(float* d, const uint32_t* a,
                                          const uint32_t* b) {
    asm volatile(
        "mma.sync.aligned.m16n8k16.row.col.f32.f16.f16.f32 "
        "{%0,%1,%2,%3}, {%4,%5,%6,%7}, {%8,%9}, {%0,%1,%2,%3};"
        : "+f"(d[0]), "+f"(d[1]), "+f"(d[2]), "+f"(d[3])
        : "r"(a[0]), "r"(a[1]), "r"(a[2]), "r"(a[3]), "r"(b[0]), "r"(b[1]));
}
__device__ __forceinline__ void cp16(uint32_t sdst, const void* gsrc) {
    asm volatile("cp.async.cg.shared.global [%0], [%1], 16;"
                 :: "r"(sdst), "l"(gsrc) : "memory");
}
#define CP_COMMIT() asm volatile("cp.async.commit_group;" ::: "memory")
#define CP_WAIT1() asm volatile("cp.async.wait_group 1;" ::: "memory")
#define CP_WAIT0() asm volatile("cp.async.wait_group 0;" ::: "memory")

__device__ __forceinline__ void ldm_x4(uint32_t* r, uint32_t a) {
    asm volatile("ldmatrix.sync.aligned.m8n8.x4.shared.b16 {%0,%1,%2,%3}, [%4];"
                 : "=r"(r[0]), "=r"(r[1]), "=r"(r[2]), "=r"(r[3]) : "r"(a));
}
__device__ __forceinline__ void ldm_x4_t(uint32_t* r, uint32_t a) {
    asm volatile("ldmatrix.sync.aligned.m8n8.x4.trans.shared.b16 {%0,%1,%2,%3}, [%4];"
                 : "=r"(r[0]), "=r"(r[1]), "=r"(r[2]), "=r"(r[3]) : "r"(a));
}
// fp32 -> packed fp16 hi/lo
__device__ __forceinline__ void split2h(float x, float y, uint32_t& hi, uint32_t& lo) {
    __half hx = __float2half_rn(x), hy = __float2half_rn(y);
    __half lx = __float2half_rn(x - __half2float(hx));
    __half ly = __float2half_rn(y - __half2float(hy));
    hi = (uint32_t)__half_as_ushort(hx) | ((uint32_t)__half_as_ushort(hy) << 16);
    lo = (uint32_t)__half_as_ushort(lx) | ((uint32_t)__half_as_ushort(ly) << 16);
}
__device__ __forceinline__ uint32_t pack_h2(float x, float y) {
    return (uint32_t)__half_as_ushort(__float2half_rn(x)) |
           ((uint32_t)__half_as_ushort(__float2half_rn(y)) << 16);
}

// ---------------- split kernels ----------------
__global__ void xsplit_kernel(const float* __restrict__ x,
                              __half* __restrict__ h, __half* __restrict__ l,
                              int n) {
    int i = blockIdx.x * blockDim.x + threadIdx.x;
    if (i < n) {
        float v = x[i];
        __half hh = __float2half_rn(v);
        h[i] = hh;
        l[i] = __float2half_rn(v - __half2float(hh));
    }
}

// w [Kdim, Ndim] fp32 -> th [Ndim, Kdim] single fp16 (transposed)
__global__ void wsplit_kernel(const float* __restrict__ w,
                              __half* __restrict__ th, int Kdim, int Ndim) {
    __shared__ float t[32][33];
    int n0 = blockIdx.x * 32, k0 = blockIdx.y * 32;
    int tx = threadIdx.x, ty = threadIdx.y;  // 32 x 8
#pragma unroll
    for (int i = 0; i < 32; i += 8)
        t[ty + i][tx] = w[(size_t)(k0 + ty + i) * Ndim + n0 + tx];
    __syncthreads();
#pragma unroll
    for (int i = 0; i < 32; i += 8)
        th[(size_t)(n0 + ty + i) * Kdim + k0 + tx] = __float2half_rn(t[tx][ty + i]);
}

// ---------------- fp16 2-term mma.sync GEMM (unchanged from R15 pass) ----------
#define COMP_BYTES (128 * 80)
#define BUF_BYTES (3 * COMP_BYTES)
#define GEMM_SMEM (2 * BUF_BYTES) /* 61440 */

__device__ __forceinline__ void load_chunk_async(
    const __half* Ah, const __half* Al, const __half* Bh,
    int K, int kc, uint32_t sbuf, int tid) {
    const __half* gp[3] = {Ah, Al, Bh};
#pragma unroll
    for (int comp = 0; comp < 3; comp++) {
#pragma unroll
        for (int i = 0; i < 2; i++) {
            int id = tid + (i << 8);
            int r = id >> 2, c = id & 3;
            cp16(sbuf + comp * COMP_BYTES + r * 80 + c * 16,
                 gp[comp] + (size_t)r * K + kc + c * 8);
        }
    }
}

__global__ __launch_bounds__(256) void gemm_f16x2_kernel(
    const __half* __restrict__ Ah, const __half* __restrict__ Al,
    const __half* __restrict__ Bh, float* __restrict__ C, int N, int K) {
    extern __shared__ char smem[];
    const uint32_t sb = smem_u32(smem);
    const int tid = threadIdx.x;
    const int wid = tid >> 5, lane = tid & 31;
    const int wm = wid >> 2, wn = wid & 3;
    const int g8 = lane >> 3, l8 = lane & 7;
    const int bm = blockIdx.y << 7, bn = blockIdx.x << 7;

    const __half* pAh = Ah + (size_t)bm * K;
    const __half* pAl = Al + (size_t)bm * K;
    const __half* pBh = Bh + (size_t)bn * K;

    float acc[4][4][4];
#pragma unroll
    for (int mt = 0; mt < 4; mt++)
#pragma unroll
        for (int nt = 0; nt < 4; nt++)
#pragma unroll
            for (int i = 0; i < 4; i++) acc[mt][nt][i] = 0.f;

    const int NC = K >> 5;
    load_chunk_async(pAh, pAl, pBh, K, 0, sb, tid);
    CP_COMMIT();

    const uint32_t aOff = (uint32_t)((wm * 64 + (g8 & 1) * 8 + l8) * 80 + (g8 >> 1) * 16);
    const uint32_t bOff = (uint32_t)((wn * 32 + (g8 >> 1) * 8 + l8) * 80 + (g8 & 1) * 16);

    for (int c = 0; c < NC; c++) {
        const uint32_t buf = sb + (uint32_t)(c & 1) * BUF_BYTES;
        if (c + 1 < NC) {
            load_chunk_async(pAh, pAl, pBh, K, (c + 1) << 5,
                             sb + (uint32_t)((c + 1) & 1) * BUF_BYTES, tid);
            CP_COMMIT();
            CP_WAIT1();
        } else {
            CP_WAIT0();
        }
        __syncthreads();

#pragma unroll
        for (int ks = 0; ks < 2; ks++) {
            const uint32_t kb = (uint32_t)(ks * 32);
            uint32_t ah[4][4], al[4][4], bh[2][4];
#pragma unroll
            for (int mt = 0; mt < 4; mt++) {
                uint32_t ao = buf + aOff + (uint32_t)(mt * 16 * 80) + kb;
                ldm_x4(ah[mt], ao);
                ldm_x4(al[mt], ao + COMP_BYTES);
            }
#pragma unroll
            for (int ntp = 0; ntp < 2; ntp++) {
                uint32_t bo = buf + bOff + (uint32_t)(ntp * 16 * 80) + kb;
                ldm_x4(bh[ntp], bo + 2 * COMP_BYTES);
            }
#pragma unroll
            for (int mt = 0; mt < 4; mt++)
#pragma unroll
                for (int ntp = 0; ntp < 2; ntp++) {
                    mma16816h(acc[mt][2 * ntp], ah[mt], bh[ntp]);
                    mma16816h(acc[mt][2 * ntp], al[mt], bh[ntp]);
                    mma16816h(acc[mt][2 * ntp + 1], ah[mt], bh[ntp] + 2);
                    mma16816h(acc[mt][2 * ntp + 1], al[mt], bh[ntp] + 2);
                }
        }
        __syncthreads();
    }

#pragma unroll
    for (int mt = 0; mt < 4; mt++) {
        int row = bm + wm * 64 + mt * 16 + (lane >> 2);
#pragma unroll
        for (int nt = 0; nt < 4; nt++) {
            int col = bn + wn * 32 + nt * 8 + (lane & 3) * 2;
            *(float2*)(C + (size_t)row * N + col) =
                make_float2(acc[mt][nt][0], acc[mt][nt][1]);
            *(float2*)(C + (size_t)(row + 8) * N + col) =
                make_float2(acc[mt][nt][2], acc[mt][nt][3]);
        }
    }
}

// ---------------- RoPE on Q (in g_QKV), fp32 in-place ----------------
__global__ void rope_q_kernel(float* __restrict__ QKV,
                              const float* __restrict__ cosv,
                              const float* __restrict__ sinv) {
    const int qn = S * HQ * (HD / 2);
    int idx = blockIdx.x * blockDim.x + threadIdx.x;
    if (idx < qn) {
        int i = idx & 63;
        int h = (idx >> 6) & (HQ - 1);
        int s = idx >> 11;
        float c = cosv[(s << 6) + i];
        float sn = sinv[(s << 6) + i];
        float2* p = (float2*)(QKV + (size_t)s * QD + h * HD) + i;
        float2 v = *p;
        *p = make_float2(v.x * c - v.y * sn, v.x * sn + v.y * c);
    }
}

// ---------------- K rope + fp16 hi/lo split; V single fp16 ----------------
__global__ void kvsplit_kernel(const float* __restrict__ QKV,
                               const float* __restrict__ cosv,
                               const float* __restrict__ sinv,
                               uint32_t* __restrict__ Kh, uint32_t* __restrict__ Kl,
                               uint32_t* __restrict__ Vh) {
    const int n = S * 512;  // pairs per tensor
    int idx = blockIdx.x * blockDim.x + threadIdx.x;
    if (idx < n) {  // K with rope, hi/lo
        int pc = idx & 511, s = idx >> 9;
        int i = pc & 63;
        float2 v = *(const float2*)(QKV + (size_t)s * QD + 4096 + pc * 2);
        float c = cosv[(s << 6) + i], sn = sinv[(s << 6) + i];
        uint32_t hw, lw;
        split2h(v.x * c - v.y * sn, v.x * sn + v.y * c, hw, lw);
        Kh[idx] = hw;
        Kl[idx] = lw;
    } else if (idx < 2 * n) {  // V single fp16
        int t = idx - n;
        int pc = t & 511, s = t >> 9;
        float2 v = *(const float2*)(QKV + (size_t)s * QD + 5120 + pc * 2);
        Vh[t] = pack_h2(v.x, v.y);
    }
}

// ---------------- Flash attention ----------------
// Scores fully compensated (Qh*Kh + Qh*Kl + Ql*Kh); PV single-precision fp16
// (P single, V single): 128 mma/warp/tile vs 192. Heaviest q-tiles first.
#define QK_STR 272 /* bytes per 128-col f16 row */
#define P_STR 144
#define PS_STR 68
#define OFF_QH 0
#define OFF_QL 17408
#define OFF_KV 34816
#define KV_STAGE 52224
#define ST_KH 0
#define ST_KL 17408
#define ST_VH 34816
#define OFF_PS 139264
#define OFF_PB 156672
#define OFF_FR 165888
#define OFF_IL 166144
#define ATTN2_SMEM 166400

__device__ __forceinline__ void issue_kv(const uint32_t* const* gp, int k0, int kvh,
                                         uint32_t stage, int tid) {
#pragma unroll
    for (int a = 0; a < 3; a++)
#pragma unroll
        for (int j = 0; j < 4; j++) {
            int id = tid + (j << 8);
            int r = id >> 4, c = id & 15;
            cp16(stage + a * 17408 + r * QK_STR + c * 16,
                 gp[a] + (size_t)(k0 + r) * 512 + kvh * 64 + c * 4);
        }
}

__global__ __launch_bounds__(256) void attn_mma_kernel(
    const float* __restrict__ Qg, const uint32_t* __restrict__ Khg,
    const uint32_t* __restrict__ Klg, const uint32_t* __restrict__ Vhg,
    __half* __restrict__ Oh, __half* __restrict__ Ol) {
    extern __shared__ char smb[];
    const uint32_t sb = smem_u32(smb);
    const int tid = threadIdx.x, wid = tid >> 5, lane = tid & 31;
    const int h = blockIdx.y;
    const int q0 = (int)(gridDim.x - 1 - blockIdx.x) * 64;  // heaviest first
    const int kvh = h >> 2;
    const int wm = wid & 3, wn = wid >> 2;
    const int g8 = lane >> 3, l8 = lane & 7;
    const int row = tid >> 2, lr = tid & 3;
    const int r0 = wm * 16 + (lane >> 2);
    const float scale = 0.08838834764831845f;  // 1/sqrt(128)

    float* fRp = (float*)(smb + OFF_FR);
    float* iLp = (float*)(smb + OFF_IL);

    // load Q tile, fp16 hi/lo split
    for (int i = tid; i < 2048; i += 256) {
        int r = i >> 5, c4 = (i & 31) << 2;
        float4 q = *(const float4*)(Qg + (size_t)(q0 + r) * QD + h * HD + c4);
        uint32_t h0, l0, h1, l1;
        split2h(q.x, q.y, h0, l0);
        split2h(q.z, q.w, h1, l1);
        *(uint2*)(smb + OFF_QH + r * QK_STR + c4 * 2) = make_uint2(h0, h1);
        *(uint2*)(smb + OFF_QL + r * QK_STR + c4 * 2) = make_uint2(l0, l1);
    }

    float m_i = -CUDART_INF_F, l_i = 0.f;
    float oacc[8][4];
#pragma unroll
    for (int nt = 0; nt < 8; nt++)
#pragma unroll
        for (int i = 0; i < 4; i++) oacc[nt][i] = 0.f;

    const uint32_t aRow = (uint32_t)(wm * 16 + (g8 & 1) * 8 + l8);
    const uint32_t qhB = sb + OFF_QH + aRow * QK_STR;
    const uint32_t qlB = sb + OFF_QL + aRow * QK_STR;
    const uint32_t phB = sb + OFF_PB + aRow * P_STR;
    const uint32_t aColOfs = (uint32_t)((g8 >> 1) * 8) * 2;

    const uint32_t* gp[3] = {Khg, Klg, Vhg};
    issue_kv(gp, 0, kvh, sb + OFF_KV, tid);
    CP_COMMIT();

    for (int k0 = 0; k0 <= q0; k0 += 64) {
        const int it = k0 >> 6;
        const uint32_t stage = sb + OFF_KV + (uint32_t)(it & 1) * KV_STAGE;
        __syncthreads();
        if (k0 + 64 <= q0) {
            issue_kv(gp, k0 + 64, kvh, sb + OFF_KV + (uint32_t)((it + 1) & 1) * KV_STAGE,
                     tid);
            CP_COMMIT();
            CP_WAIT1();
        } else {
            CP_WAIT0();
        }
        __syncthreads();

        // ---- scores: S = Q K^T (Qh*Kh + Qh*Kl + Ql*Kh) ----
        float sacc[4][4];
#pragma unroll
        for (int nt = 0; nt < 4; nt++)
#pragma unroll
            for (int i = 0; i < 4; i++) sacc[nt][i] = 0.f;

#pragma unroll
        for (int ks = 0; ks < 8; ks++) {
            uint32_t aH[4], aL[4];
            uint32_t co = (uint32_t)(ks * 16) * 2 + aColOfs;
            ldm_x4(aH, qhB + co);
            ldm_x4(aL, qlB + co);
#pragma unroll
            for (int ntp = 0; ntp < 2; ntp++) {
                uint32_t bH[4], bL[4];
                uint32_t nrow = (uint32_t)(wn * 32 + ntp * 16 + (g8 >> 1) * 8 + l8);
                uint32_t kof = (uint32_t)(ks * 16 + (g8 & 1) * 8) * 2;
                ldm_x4(bH, stage + ST_KH + nrow * QK_STR + kof);
                ldm_x4(bL, stage + ST_KL + nrow * QK_STR + kof);
                mma16816h(sacc[2 * ntp], aH, bH);
                mma16816h(sacc[2 * ntp], aH, bL);
                mma16816h(sacc[2 * ntp], aL, bH);
                mma16816h(sacc[2 * ntp + 1], aH, bH + 2);
                mma16816h(sacc[2 * ntp + 1], aH, bL + 2);
                mma16816h(sacc[2 * ntp + 1], aL, bH + 2);
            }
        }
        {
            float* Ps = (float*)(smb + OFF_PS);
            int qr0 = q0 + r0, qr1 = qr0 + 8;
#pragma unroll
            for (int nt = 0; nt < 4; nt++) {
                int c = wn * 32 + nt * 8 + (lane & 3) * 2;
                int kc = k0 + c;
                Ps[r0 * PS_STR + c] = (kc <= qr0) ? sacc[nt][0] * scale : -CUDART_INF_F;
                Ps[r0 * PS_STR + c + 1] =
                    (kc + 1 <= qr0) ? sacc[nt][1] * scale : -CUDART_INF_F;
                Ps[(r0 + 8) * PS_STR + c] =
                    (kc <= qr1) ? sacc[nt][2] * scale : -CUDART_INF_F;
                Ps[(r0 + 8) * PS_STR + c + 1] =
                    (kc + 1 <= qr1) ? sacc[nt][3] * scale : -CUDART_INF_F;
            }
        }
        __syncthreads();

        // ---- online softmax (P stored single fp16) ----
        {
            const float* prow = (const float*)(smb + OFF_PS) + row * PS_STR + lr * 16;
            float pv[16];
            float rmax = -CUDART_INF_F;
#pragma unroll
            for (int j = 0; j < 16; j++) {
                pv[j] = prow[j];
                rmax = fmaxf(rmax, pv[j]);
            }
            rmax = fmaxf(rmax, __shfl_xor_sync(0xffffffff, rmax, 1));
            rmax = fmaxf(rmax, __shfl_xor_sync(0xffffffff, rmax, 2));
            float m_new = fmaxf(m_i, rmax);
            float rsum = 0.f;
#pragma unroll
            for (int j = 0; j < 16; j++) {
                pv[j] = __expf(pv[j] - m_new);
                rsum += pv[j];
            }
            rsum += __shfl_xor_sync(0xffffffff, rsum, 1);
            rsum += __shfl_xor_sync(0xffffffff, rsum, 2);
            float f = __expf(m_i - m_new);
            l_i = l_i * f + rsum;
            m_i = m_new;
            if (lr == 0) fRp[row] = f;
#pragma unroll
            for (int j = 0; j < 8; j++) {
                *(uint32_t*)(smb + OFF_PB + row * P_STR + (lr * 16 + 2 * j) * 2) =
                    pack_h2(pv[2 * j], pv[2 * j + 1]);
            }
        }
        __syncthreads();

        // ---- PV: O = P * Vh (single-precision fp16 path), online rescale ----
        {
            float f0 = fRp[r0], f1 = fRp[r0 + 8];
#pragma unroll
            for (int nt = 0; nt < 8; nt++) {
                oacc[nt][0] *= f0;
                oacc[nt][1] *= f0;
                oacc[nt][2] *= f1;
                oacc[nt][3] *= f1;
            }
#pragma unroll
            for (int ks = 0; ks < 4; ks++) {
                uint32_t aP[4];
                uint32_t po = (uint32_t)(ks * 16) * 2 + ((uint32_t)((g8 >> 1) * 8) * 2);
                ldm_x4(aP, phB + po);
                uint32_t krow = (uint32_t)(ks * 16 + (g8 & 1) * 8 + l8);
#pragma unroll
                for (int ntp = 0; ntp < 4; ntp++) {
                    uint32_t bH[4];
                    uint32_t ncol = (uint32_t)(wn * 64 + ntp * 16 + (g8 >> 1) * 8);
                    ldm_x4_t(bH, stage + ST_VH + krow * QK_STR + ncol * 2);
                    mma16816h(oacc[2 * ntp], aP, bH);
                    mma16816h(oacc[2 * ntp + 1], aP, bH + 2);
                }
            }
        }
    }

    if (lr == 0) iLp[row] = 1.f / l_i;
    __syncthreads();

    // finalize: scale by 1/l, write fp16 hi/lo (feeds wo GEMM A-side)
    {
        float i0 = iLp[r0], i1 = iLp[r0 + 8];
#pragma unroll
        for (int nt = 0; nt < 8; nt++) {
            int col = h * HD + wn * 64 + nt * 8 + (lane & 3) * 2;
            size_t o0 = (size_t)(q0 + r0) * D + col;
            size_t o1 = (size_t)(q0 + r0 + 8) * D + col;
            uint32_t hh, ll;
            split2h(oacc[nt][0] * i0, oacc[nt][1] * i0, hh, ll);
            *(uint32_t*)(Oh + o0) = hh;
            *(uint32_t*)(Ol + o0) = ll;
            split2h(oacc[nt][2] * i1, oacc[nt][3] * i1, hh, ll);
            *(uint32_t*)(Oh + o1) = hh;
            *(uint32_t*)(Ol + o1) = ll;
        }
    }
}

// ---------------- launch ----------------
extern "C" void kernel_launch(void* const* d_in, const int* in_sizes, int n_in,
                              void* d_out, int out_size) {
    const float* x = (const float*)d_in[0];
    const float* wq = (const float*)d_in[1];
    const float* wk = (const float*)d_in[2];
    const float* wv = (const float*)d_in[3];
    const float* wo = (const float*)d_in[4];
    const float* cosv = (const float*)d_in[5];
    const float* sinv = (const float*)d_in[6];
    float* out = (float*)d_out;

    float* pQKV;
    cudaGetSymbolAddress((void**)&pQKV, g_QKV);
    __half *pXh, *pXl, *pWh, *pWoh;
    cudaGetSymbolAddress((void**)&pXh, g_Xh);
    cudaGetSymbolAddress((void**)&pXl, g_Xl);
    cudaGetSymbolAddress((void**)&pWh, g_Wh);
    cudaGetSymbolAddress((void**)&pWoh, g_Woh);
    uint32_t *pKh, *pKl, *pVh;
    cudaGetSymbolAddress((void**)&pKh, g_Kh16);
    cudaGetSymbolAddress((void**)&pKl, g_Kl16);
    cudaGetSymbolAddress((void**)&pVh, g_Vh16);

    cudaFuncSetAttribute(gemm_f16x2_kernel,
                         cudaFuncAttributeMaxDynamicSharedMemorySize, GEMM_SMEM);
    cudaFuncSetAttribute(attn_mma_kernel,
                         cudaFuncAttributeMaxDynamicSharedMemorySize, ATTN2_SMEM);

    // x split (fp16 hi/lo) + transposed single-fp16 weights
    {
        int n = S * D;
        xsplit_kernel<<<(n + 255) / 256, 256>>>(x, pXh, pXl, n);
    }
    wsplit_kernel<<<dim3(D / 32, D / 32), dim3(32, 8)>>>(wq, pWh, D, D);
    wsplit_kernel<<<dim3(KV_W / 32, D / 32), dim3(32, 8)>>>(
        wk, pWh + (size_t)4096 * D, D, KV_W);
    wsplit_kernel<<<dim3(KV_W / 32, D / 32), dim3(32, 8)>>>(
        wv, pWh + (size_t)5120 * D, D, KV_W);
    wsplit_kernel<<<dim3(D / 32, D / 32), dim3(32, 8)>>>(wo, pWoh, D, D);

    // combined QKV projection (fp16 2-term GEMM, N=6144)
    gemm_f16x2_kernel<<<dim3(QD / 128, S / 128), 256, GEMM_SMEM>>>(
        pXh, pXl, pWh, pQKV, QD, D);

    // RoPE on Q; K rope + fp16 hi/lo split; V single fp16
    {
        int qn = S * HQ * (HD / 2);
        rope_q_kernel<<<(qn + 255) / 256, 256>>>(pQKV, cosv, sinv);
        int kvn = 2 * S * 512;
        kvsplit_kernel<<<(kvn + 255) / 256, 256>>>(pQKV, cosv, sinv, pKh, pKl, pVh);
    }

    // attention (compensated scores, single-fp16 PV; writes fp16 hi/lo)
    attn_mma_kernel<<<dim3(S / 64, HQ), 256, ATTN2_SMEM>>>(pQKV, pKh, pKl, pVh,
                                                           pXh, pXl);

    // output projection (fp16 2-term GEMM)
    gemm_f16x2_kernel<<<dim3(D / 128, S / 128), 256, GEMM_SMEM>>>(
        pXh, pXl, pWoh, out, D, D);
}

// round 17
// speedup vs baseline: 7.7552x; 1.1595x over previous
#include <cuda_runtime.h>
#include <cuda_bf16.h>
#include <cuda_fp16.h>
#include <math_constants.h>
#include <cstdint>
#include <cstddef>

#define S 2048
#define D 4096
#define HQ 32
#define HKV 8
#define HD 128
#define KV_W (HKV * HD) /* 1024 */
#define QD 6144         /* combined QKV output width */

// ---------------- scratch (no allocations allowed) ----------------
__device__ float g_QKV[(size_t)S * QD];  // Q | K | V fp32 (50 MB)

// fp16 planes
__device__ __half g_Xh[(size_t)S * D], g_Xl[(size_t)S * D];  // x(single); attn out hi/lo
__device__ __half g_Wh[(size_t)QD * D];   // [Wq;Wk;Wv]^T single fp16
__device__ __half g_Woh[(size_t)D * D];   // Wo^T single fp16

// pre-split fp16 K (hi/lo) and V (single) for attention
__device__ uint32_t g_Kh16[(size_t)S * 512], g_Kl16[(size_t)S * 512];
__device__ uint32_t g_Vh16[(size_t)S * 512];

// ---------------- mma.sync / cp.async / ldmatrix helpers ----------------
__device__ __forceinline__ uint32_t smem_u32(const void* p) {
    uint32_t a;
    asm("{ .reg .u64 t; cvta.to.shared.u64 t, %1; cvt.u32.u64 %0, t; }"
        : "=r"(a) : "l"(p));
    return a;
}
__device__ __forceinline__ void mma16816h(float* d, const uint32_t* a,
                                          const uint32_t* b) {
    asm volatile(
        "mma.sync.aligned.m16n8k16.row.col.f32.f16.f16.f32 "
        "{%0,%1,%2,%3}, {%4,%5,%6,%7}, {%8,%9}, {%0,%1,%2,%3};"
        : "+f"(d[0]), "+f"(d[1]), "+f"(d[2]), "+f"(d[3])
        : "r"(a[0]), "r"(a[1]), "r"(a[2]), "r"(a[3]), "r"(b[0]), "r"(b[1]));
}
__device__ __forceinline__ void cp16(uint32_t sdst, const void* gsrc) {
    asm volatile("cp.async.cg.shared.global [%0], [%1], 16;"
                 :: "r"(sdst), "l"(gsrc) : "memory");
}
#define CP_COMMIT() asm volatile("cp.async.commit_group;" ::: "memory")
#define CP_WAIT1() asm volatile("cp.async.wait_group 1;" ::: "memory")
#define CP_WAIT0() asm volatile("cp.async.wait_group 0;" ::: "memory")

__device__ __forceinline__ void ldm_x4(uint32_t* r, uint32_t a) {
    asm volatile("ldmatrix.sync.aligned.m8n8.x4.shared.b16 {%0,%1,%2,%3}, [%4];"
                 : "=r"(r[0]), "=r"(r[1]), "=r"(r[2]), "=r"(r[3]) : "r"(a));
}
__device__ __forceinline__ void ldm_x4_t(uint32_t* r, uint32_t a) {
    asm volatile("ldmatrix.sync.aligned.m8n8.x4.trans.shared.b16 {%0,%1,%2,%3}, [%4];"
                 : "=r"(r[0]), "=r"(r[1]), "=r"(r[2]), "=r"(r[3]) : "r"(a));
}
__device__ __forceinline__ void split2h(float x, float y, uint32_t& hi, uint32_t& lo) {
    __half hx = __float2half_rn(x), hy = __float2half_rn(y);
    __half lx = __float2half_rn(x - __half2float(hx));
    __half ly = __float2half_rn(y - __half2float(hy));
    hi = (uint32_t)__half_as_ushort(hx) | ((uint32_t)__half_as_ushort(hy) << 16);
    lo = (uint32_t)__half_as_ushort(lx) | ((uint32_t)__half_as_ushort(ly) << 16);
}
__device__ __forceinline__ uint32_t pack_h2(float x, float y) {
    return (uint32_t)__half_as_ushort(__float2half_rn(x)) |
           ((uint32_t)__half_as_ushort(__float2half_rn(y)) << 16);
}

// ---------------- split kernels ----------------
// x -> single fp16 (QKV GEMM A-side)
__global__ void xcast_kernel(const float* __restrict__ x, __half* __restrict__ h,
                             int n) {
    int i = blockIdx.x * blockDim.x + threadIdx.x;
    if (i < n) h[i] = __float2half_rn(x[i]);
}

// w [Kdim, Ndim] fp32 -> th [Ndim, Kdim] single fp16 (transposed)
__global__ void wsplit_kernel(const float* __restrict__ w,
                              __half* __restrict__ th, int Kdim, int Ndim) {
    __shared__ float t[32][33];
    int n0 = blockIdx.x * 32, k0 = blockIdx.y * 32;
    int tx = threadIdx.x, ty = threadIdx.y;  // 32 x 8
#pragma unroll
    for (int i = 0; i < 32; i += 8)
        t[ty + i][tx] = w[(size_t)(k0 + ty + i) * Ndim + n0 + tx];
    __syncthreads();
#pragma unroll
    for (int i = 0; i < 32; i += 8)
        th[(size_t)(n0 + ty + i) * Kdim + k0 + tx] = __float2half_rn(t[tx][ty + i]);
}

// ---------------- GEMM smem geometry (shared by both variants) -------------
#define COMP_BYTES (128 * 80)

// ============ single x single fp16 GEMM (QKV projection) ============
#define BUF1_BYTES (2 * COMP_BYTES)
#define GEMM1_SMEM (2 * BUF1_BYTES) /* 40960 */

__device__ __forceinline__ void load_chunk1(const __half* A, const __half* B,
                                            int K, int kc, uint32_t sbuf, int tid) {
    const __half* gp[2] = {A, B};
#pragma unroll
    for (int comp = 0; comp < 2; comp++) {
#pragma unroll
        for (int i = 0; i < 2; i++) {
            int id = tid + (i << 8);
            int r = id >> 2, c = id & 3;
            cp16(sbuf + comp * COMP_BYTES + r * 80 + c * 16,
                 gp[comp] + (size_t)r * K + kc + c * 8);
        }
    }
}

__global__ __launch_bounds__(256) void gemm_f16_kernel(
    const __half* __restrict__ A, const __half* __restrict__ B,
    float* __restrict__ C, int N, int K) {
    extern __shared__ char smem[];
    const uint32_t sb = smem_u32(smem);
    const int tid = threadIdx.x;
    const int wid = tid >> 5, lane = tid & 31;
    const int wm = wid >> 2, wn = wid & 3;
    const int g8 = lane >> 3, l8 = lane & 7;
    const int bm = blockIdx.y << 7, bn = blockIdx.x << 7;

    const __half* pA = A + (size_t)bm * K;
    const __half* pB = B + (size_t)bn * K;

    float acc[4][4][4];
#pragma unroll
    for (int mt = 0; mt < 4; mt++)
#pragma unroll
        for (int nt = 0; nt < 4; nt++)
#pragma unroll
            for (int i = 0; i < 4; i++) acc[mt][nt][i] = 0.f;

    const int NC = K >> 5;
    load_chunk1(pA, pB, K, 0, sb, tid);
    CP_COMMIT();

    const uint32_t aOff = (uint32_t)((wm * 64 + (g8 & 1) * 8 + l8) * 80 + (g8 >> 1) * 16);
    const uint32_t bOff = (uint32_t)((wn * 32 + (g8 >> 1) * 8 + l8) * 80 + (g8 & 1) * 16);

    for (int c = 0; c < NC; c++) {
        const uint32_t buf = sb + (uint32_t)(c & 1) * BUF1_BYTES;
        if (c + 1 < NC) {
            load_chunk1(pA, pB, K, (c + 1) << 5,
                        sb + (uint32_t)((c + 1) & 1) * BUF1_BYTES, tid);
            CP_COMMIT();
            CP_WAIT1();
        } else {
            CP_WAIT0();
        }
        __syncthreads();

#pragma unroll
        for (int ks = 0; ks < 2; ks++) {
            const uint32_t kb = (uint32_t)(ks * 32);
            uint32_t ah[4][4], bh[2][4];
#pragma unroll
            for (int mt = 0; mt < 4; mt++)
                ldm_x4(ah[mt], buf + aOff + (uint32_t)(mt * 16 * 80) + kb);
#pragma unroll
            for (int ntp = 0; ntp < 2; ntp++)
                ldm_x4(bh[ntp], buf + bOff + (uint32_t)(ntp * 16 * 80) + kb + COMP_BYTES);
#pragma unroll
            for (int mt = 0; mt < 4; mt++)
#pragma unroll
                for (int ntp = 0; ntp < 2; ntp++) {
                    mma16816h(acc[mt][2 * ntp], ah[mt], bh[ntp]);
                    mma16816h(acc[mt][2 * ntp + 1], ah[mt], bh[ntp] + 2);
                }
        }
        __syncthreads();
    }

#pragma unroll
    for (int mt = 0; mt < 4; mt++) {
        int row = bm + wm * 64 + mt * 16 + (lane >> 2);
#pragma unroll
        for (int nt = 0; nt < 4; nt++) {
            int col = bn + wn * 32 + nt * 8 + (lane & 3) * 2;
            *(float2*)(C + (size_t)row * N + col) =
                make_float2(acc[mt][nt][0], acc[mt][nt][1]);
            *(float2*)(C + (size_t)(row + 8) * N + col) =
                make_float2(acc[mt][nt][2], acc[mt][nt][3]);
        }
    }
}

// ============ 2-term fp16 GEMM: C = (Ah+Al).Bh (WO projection) ============
#define BUF_BYTES (3 * COMP_BYTES)
#define GEMM_SMEM (2 * BUF_BYTES) /* 61440 */

__device__ __forceinline__ void load_chunk_async(
    const __half* Ah, const __half* Al, const __half* Bh,
    int K, int kc, uint32_t sbuf, int tid) {
    const __half* gp[3] = {Ah, Al, Bh};
#pragma unroll
    for (int comp = 0; comp < 3; comp++) {
#pragma unroll
        for (int i = 0; i < 2; i++) {
            int id = tid + (i << 8);
            int r = id >> 2, c = id & 3;
            cp16(sbuf + comp * COMP_BYTES + r * 80 + c * 16,
                 gp[comp] + (size_t)r * K + kc + c * 8);
        }
    }
}

__global__ __launch_bounds__(256) void gemm_f16x2_kernel(
    const __half* __restrict__ Ah, const __half* __restrict__ Al,
    const __half* __restrict__ Bh, float* __restrict__ C, int N, int K) {
    extern __shared__ char smem[];
    const uint32_t sb = smem_u32(smem);
    const int tid = threadIdx.x;
    const int wid = tid >> 5, lane = tid & 31;
    const int wm = wid >> 2, wn = wid & 3;
    const int g8 = lane >> 3, l8 = lane & 7;
    const int bm = blockIdx.y << 7, bn = blockIdx.x << 7;

    const __half* pAh = Ah + (size_t)bm * K;
    const __half* pAl = Al + (size_t)bm * K;
    const __half* pBh = Bh + (size_t)bn * K;

    float acc[4][4][4];
#pragma unroll
    for (int mt = 0; mt < 4; mt++)
#pragma unroll
        for (int nt = 0; nt < 4; nt++)
#pragma unroll
            for (int i = 0; i < 4; i++) acc[mt][nt][i] = 0.f;

    const int NC = K >> 5;
    load_chunk_async(pAh, pAl, pBh, K, 0, sb, tid);
    CP_COMMIT();

    const uint32_t aOff = (uint32_t)((wm * 64 + (g8 & 1) * 8 + l8) * 80 + (g8 >> 1) * 16);
    const uint32_t bOff = (uint32_t)((wn * 32 + (g8 >> 1) * 8 + l8) * 80 + (g8 & 1) * 16);

    for (int c = 0; c < NC; c++) {
        const uint32_t buf = sb + (uint32_t)(c & 1) * BUF_BYTES;
        if (c + 1 < NC) {
            load_chunk_async(pAh, pAl, pBh, K, (c + 1) << 5,
                             sb + (uint32_t)((c + 1) & 1) * BUF_BYTES, tid);
            CP_COMMIT();
            CP_WAIT1();
        } else {
            CP_WAIT0();
        }
        __syncthreads();

#pragma unroll
        for (int ks = 0; ks < 2; ks++) {
            const uint32_t kb = (uint32_t)(ks * 32);
            uint32_t ah[4][4], al[4][4], bh[2][4];
#pragma unroll
            for (int mt = 0; mt < 4; mt++) {
                uint32_t ao = buf + aOff + (uint32_t)(mt * 16 * 80) + kb;
                ldm_x4(ah[mt], ao);
                ldm_x4(al[mt], ao + COMP_BYTES);
            }
#pragma unroll
            for (int ntp = 0; ntp < 2; ntp++) {
                uint32_t bo = buf + bOff + (uint32_t)(ntp * 16 * 80) + kb;
                ldm_x4(bh[ntp], bo + 2 * COMP_BYTES);
            }
#pragma unroll
            for (int mt = 0; mt < 4; mt++)
#pragma unroll
                for (int ntp = 0; ntp < 2; ntp++) {
                    mma16816h(acc[mt][2 * ntp], ah[mt], bh[ntp]);
                    mma16816h(acc[mt][2 * ntp], al[mt], bh[ntp]);
                    mma16816h(acc[mt][2 * ntp + 1], ah[mt], bh[ntp] + 2);
                    mma16816h(acc[mt][2 * ntp + 1], al[mt], bh[ntp] + 2);
                }
        }
        __syncthreads();
    }

#pragma unroll
    for (int mt = 0; mt < 4; mt++) {
        int row = bm + wm * 64 + mt * 16 + (lane >> 2);
#pragma unroll
        for (int nt = 0; nt < 4; nt++) {
            int col = bn + wn * 32 + nt * 8 + (lane & 3) * 2;
            *(float2*)(C + (size_t)row * N + col) =
                make_float2(acc[mt][nt][0], acc[mt][nt][1]);
            *(float2*)(C + (size_t)(row + 8) * N + col) =
                make_float2(acc[mt][nt][2], acc[mt][nt][3]);
        }
    }
}

// ---------------- RoPE on Q (in g_QKV), fp32 in-place ----------------
__global__ void rope_q_kernel(float* __restrict__ QKV,
                              const float* __restrict__ cosv,
                              const float* __restrict__ sinv) {
    const int qn = S * HQ * (HD / 2);
    int idx = blockIdx.x * blockDim.x + threadIdx.x;
    if (idx < qn) {
        int i = idx & 63;
        int h = (idx >> 6) & (HQ - 1);
        int s = idx >> 11;
        float c = cosv[(s << 6) + i];
        float sn = sinv[(s << 6) + i];
        float2* p = (float2*)(QKV + (size_t)s * QD + h * HD) + i;
        float2 v = *p;
        *p = make_float2(v.x * c - v.y * sn, v.x * sn + v.y * c);
    }
}

// ---------------- K rope + fp16 hi/lo split; V single fp16 ----------------
__global__ void kvsplit_kernel(const float* __restrict__ QKV,
                               const float* __restrict__ cosv,
                               const float* __restrict__ sinv,
                               uint32_t* __restrict__ Kh, uint32_t* __restrict__ Kl,
                               uint32_t* __restrict__ Vh) {
    const int n = S * 512;  // pairs per tensor
    int idx = blockIdx.x * blockDim.x + threadIdx.x;
    if (idx < n) {  // K with rope, hi/lo
        int pc = idx & 511, s = idx >> 9;
        int i = pc & 63;
        float2 v = *(const float2*)(QKV + (size_t)s * QD + 4096 + pc * 2);
        float c = cosv[(s << 6) + i], sn = sinv[(s << 6) + i];
        uint32_t hw, lw;
        split2h(v.x * c - v.y * sn, v.x * sn + v.y * c, hw, lw);
        Kh[idx] = hw;
        Kl[idx] = lw;
    } else if (idx < 2 * n) {  // V single fp16
        int t = idx - n;
        int pc = t & 511, s = t >> 9;
        float2 v = *(const float2*)(QKV + (size_t)s * QD + 5120 + pc * 2);
        Vh[t] = pack_h2(v.x, v.y);
    }
}

// ---------------- Flash attention (unchanged from R16 pass) ----------------
#define QK_STR 272 /* bytes per 128-col f16 row */
#define P_STR 144
#define PS_STR 68
#define OFF_QH 0
#define OFF_QL 17408
#define OFF_KV 34816
#define KV_STAGE 52224
#define ST_KH 0
#define ST_KL 17408
#define ST_VH 34816
#define OFF_PS 139264
#define OFF_PB 156672
#define OFF_FR 165888
#define OFF_IL 166144
#define ATTN2_SMEM 166400

__device__ __forceinline__ void issue_kv(const uint32_t* const* gp, int k0, int kvh,
                                         uint32_t stage, int tid) {
#pragma unroll
    for (int a = 0; a < 3; a++)
#pragma unroll
        for (int j = 0; j < 4; j++) {
            int id = tid + (j << 8);
            int r = id >> 4, c = id & 15;
            cp16(stage + a * 17408 + r * QK_STR + c * 16,
                 gp[a] + (size_t)(k0 + r) * 512 + kvh * 64 + c * 4);
        }
}

__global__ __launch_bounds__(256) void attn_mma_kernel(
    const float* __restrict__ Qg, const uint32_t* __restrict__ Khg,
    const uint32_t* __restrict__ Klg, const uint32_t* __restrict__ Vhg,
    __half* __restrict__ Oh, __half* __restrict__ Ol) {
    extern __shared__ char smb[];
    const uint32_t sb = smem_u32(smb);
    const int tid = threadIdx.x, wid = tid >> 5, lane = tid & 31;
    const int h = blockIdx.y;
    const int q0 = (int)(gridDim.x - 1 - blockIdx.x) * 64;  // heaviest first
    const int kvh = h >> 2;
    const int wm = wid & 3, wn = wid >> 2;
    const int g8 = lane >> 3, l8 = lane & 7;
    const int row = tid >> 2, lr = tid & 3;
    const int r0 = wm * 16 + (lane >> 2);
    const float scale = 0.08838834764831845f;  // 1/sqrt(128)

    float* fRp = (float*)(smb + OFF_FR);
    float* iLp = (float*)(smb + OFF_IL);

    // load Q tile, fp16 hi/lo split
    for (int i = tid; i < 2048; i += 256) {
        int r = i >> 5, c4 = (i & 31) << 2;
        float4 q = *(const float4*)(Qg + (size_t)(q0 + r) * QD + h * HD + c4);
        uint32_t h0, l0, h1, l1;
        split2h(q.x, q.y, h0, l0);
        split2h(q.z, q.w, h1, l1);
        *(uint2*)(smb + OFF_QH + r * QK_STR + c4 * 2) = make_uint2(h0, h1);
        *(uint2*)(smb + OFF_QL + r * QK_STR + c4 * 2) = make_uint2(l0, l1);
    }

    float m_i = -CUDART_INF_F, l_i = 0.f;
    float oacc[8][4];
#pragma unroll
    for (int nt = 0; nt < 8; nt++)
#pragma unroll
        for (int i = 0; i < 4; i++) oacc[nt][i] = 0.f;

    const uint32_t aRow = (uint32_t)(wm * 16 + (g8 & 1) * 8 + l8);
    const uint32_t qhB = sb + OFF_QH + aRow * QK_STR;
    const uint32_t qlB = sb + OFF_QL + aRow * QK_STR;
    const uint32_t phB = sb + OFF_PB + aRow * P_STR;
    const uint32_t aColOfs = (uint32_t)((g8 >> 1) * 8) * 2;

    const uint32_t* gp[3] = {Khg, Klg, Vhg};
    issue_kv(gp, 0, kvh, sb + OFF_KV, tid);
    CP_COMMIT();

    for (int k0 = 0; k0 <= q0; k0 += 64) {
        const int it = k0 >> 6;
        const uint32_t stage = sb + OFF_KV + (uint32_t)(it & 1) * KV_STAGE;
        __syncthreads();
        if (k0 + 64 <= q0) {
            issue_kv(gp, k0 + 64, kvh, sb + OFF_KV + (uint32_t)((it + 1) & 1) * KV_STAGE,
                     tid);
            CP_COMMIT();
            CP_WAIT1();
        } else {
            CP_WAIT0();
        }
        __syncthreads();

        // ---- scores: S = Q K^T (Qh*Kh + Qh*Kl + Ql*Kh) ----
        float sacc[4][4];
#pragma unroll
        for (int nt = 0; nt < 4; nt++)
#pragma unroll
            for (int i = 0; i < 4; i++) sacc[nt][i] = 0.f;

#pragma unroll
        for (int ks = 0; ks < 8; ks++) {
            uint32_t aH[4], aL[4];
            uint32_t co = (uint32_t)(ks * 16) * 2 + aColOfs;
            ldm_x4(aH, qhB + co);
            ldm_x4(aL, qlB + co);
#pragma unroll
            for (int ntp = 0; ntp < 2; ntp++) {
                uint32_t bH[4], bL[4];
                uint32_t nrow = (uint32_t)(wn * 32 + ntp * 16 + (g8 >> 1) * 8 + l8);
                uint32_t kof = (uint32_t)(ks * 16 + (g8 & 1) * 8) * 2;
                ldm_x4(bH, stage + ST_KH + nrow * QK_STR + kof);
                ldm_x4(bL, stage + ST_KL + nrow * QK_STR + kof);
                mma16816h(sacc[2 * ntp], aH, bH);
                mma16816h(sacc[2 * ntp], aH, bL);
                mma16816h(sacc[2 * ntp], aL, bH);
                mma16816h(sacc[2 * ntp + 1], aH, bH + 2);
                mma16816h(sacc[2 * ntp + 1], aH, bL + 2);
                mma16816h(sacc[2 * ntp + 1], aL, bH + 2);
            }
        }
        {
            float* Ps = (float*)(smb + OFF_PS);
            int qr0 = q0 + r0, qr1 = qr0 + 8;
#pragma unroll
            for (int nt = 0; nt < 4; nt++) {
                int c = wn * 32 + nt * 8 + (lane & 3) * 2;
                int kc = k0 + c;
                Ps[r0 * PS_STR + c] = (kc <= qr0) ? sacc[nt][0] * scale : -CUDART_INF_F;
                Ps[r0 * PS_STR + c + 1] =
                    (kc + 1 <= qr0) ? sacc[nt][1] * scale : -CUDART_INF_F;
                Ps[(r0 + 8) * PS_STR + c] =
                    (kc <= qr1) ? sacc[nt][2] * scale : -CUDART_INF_F;
                Ps[(r0 + 8) * PS_STR + c + 1] =
                    (kc + 1 <= qr1) ? sacc[nt][3] * scale : -CUDART_INF_F;
            }
        }
        __syncthreads();

        // ---- online softmax (P stored single fp16) ----
        {
            const float* prow = (const float*)(smb + OFF_PS) + row * PS_STR + lr * 16;
            float pv[16];
            float rmax = -CUDART_INF_F;
#pragma unroll
            for (int j = 0; j < 16; j++) {
                pv[j] = prow[j];
                rmax = fmaxf(rmax, pv[j]);
            }
            rmax = fmaxf(rmax, __shfl_xor_sync(0xffffffff, rmax, 1));
            rmax = fmaxf(rmax, __shfl_xor_sync(0xffffffff, rmax, 2));
            float m_new = fmaxf(m_i, rmax);
            float rsum = 0.f;
#pragma unroll
            for (int j = 0; j < 16; j++) {
                pv[j] = __expf(pv[j] - m_new);
                rsum += pv[j];
            }
            rsum += __shfl_xor_sync(0xffffffff, rsum, 1);
            rsum += __shfl_xor_sync(0xffffffff, rsum, 2);
            float f = __expf(m_i - m_new);
            l_i = l_i * f + rsum;
            m_i = m_new;
            if (lr == 0) fRp[row] = f;
#pragma unroll
            for (int j = 0; j < 8; j++) {
                *(uint32_t*)(smb + OFF_PB + row * P_STR + (lr * 16 + 2 * j) * 2) =
                    pack_h2(pv[2 * j], pv[2 * j + 1]);
            }
        }
        __syncthreads();

        // ---- PV: O = P * Vh, online rescale ----
        {
            float f0 = fRp[r0], f1 = fRp[r0 + 8];
#pragma unroll
            for (int nt = 0; nt < 8; nt++) {
                oacc[nt][0] *= f0;
                oacc[nt][1] *= f0;
                oacc[nt][2] *= f1;
                oacc[nt][3] *= f1;
            }
#pragma unroll
            for (int ks = 0; ks < 4; ks++) {
                uint32_t aP[4];
                uint32_t po = (uint32_t)(ks * 16) * 2 + ((uint32_t)((g8 >> 1) * 8) * 2);
                ldm_x4(aP, phB + po);
                uint32_t krow = (uint32_t)(ks * 16 + (g8 & 1) * 8 + l8);
#pragma unroll
                for (int ntp = 0; ntp < 4; ntp++) {
                    uint32_t bH[4];
                    uint32_t ncol = (uint32_t)(wn * 64 + ntp * 16 + (g8 >> 1) * 8);
                    ldm_x4_t(bH, stage + ST_VH + krow * QK_STR + ncol * 2);
                    mma16816h(oacc[2 * ntp], aP, bH);
                    mma16816h(oacc[2 * ntp + 1], aP, bH + 2);
                }
            }
        }
    }

    if (lr == 0) iLp[row] = 1.f / l_i;
    __syncthreads();

    // finalize: scale by 1/l, write fp16 hi/lo (feeds wo GEMM A-side)
    {
        float i0 = iLp[r0], i1 = iLp[r0 + 8];
#pragma unroll
        for (int nt = 0; nt < 8; nt++) {
            int col = h * HD + wn * 64 + nt * 8 + (lane & 3) * 2;
            size_t o0 = (size_t)(q0 + r0) * D + col;
            size_t o1 = (size_t)(q0 + r0 + 8) * D + col;
            uint32_t hh, ll;
            split2h(oacc[nt][0] * i0, oacc[nt][1] * i0, hh, ll);
            *(uint32_t*)(Oh + o0) = hh;
            *(uint32_t*)(Ol + o0) = ll;
            split2h(oacc[nt][2] * i1, oacc[nt][3] * i1, hh, ll);
            *(uint32_t*)(Oh + o1) = hh;
            *(uint32_t*)(Ol + o1) = ll;
        }
    }
}

// ---------------- launch ----------------
extern "C" void kernel_launch(void* const* d_in, const int* in_sizes, int n_in,
                              void* d_out, int out_size) {
    const float* x = (const float*)d_in[0];
    const float* wq = (const float*)d_in[1];
    const float* wk = (const float*)d_in[2];
    const float* wv = (const float*)d_in[3];
    const float* wo = (const float*)d_in[4];
    const float* cosv = (const float*)d_in[5];
    const float* sinv = (const float*)d_in[6];
    float* out = (float*)d_out;

    float* pQKV;
    cudaGetSymbolAddress((void**)&pQKV, g_QKV);
    __half *pXh, *pXl, *pWh, *pWoh;
    cudaGetSymbolAddress((void**)&pXh, g_Xh);
    cudaGetSymbolAddress((void**)&pXl, g_Xl);
    cudaGetSymbolAddress((void**)&pWh, g_Wh);
    cudaGetSymbolAddress((void**)&pWoh, g_Woh);
    uint32_t *pKh, *pKl, *pVh;
    cudaGetSymbolAddress((void**)&pKh, g_Kh16);
    cudaGetSymbolAddress((void**)&pKl, g_Kl16);
    cudaGetSymbolAddress((void**)&pVh, g_Vh16);

    cudaFuncSetAttribute(gemm_f16_kernel,
                         cudaFuncAttributeMaxDynamicSharedMemorySize, GEMM1_SMEM);
    cudaFuncSetAttribute(gemm_f16x2_kernel,
                         cudaFuncAttributeMaxDynamicSharedMemorySize, GEMM_SMEM);
    cudaFuncSetAttribute(attn_mma_kernel,
                         cudaFuncAttributeMaxDynamicSharedMemorySize, ATTN2_SMEM);

    // x -> single fp16; transposed single-fp16 weights
    {
        int n = S * D;
        xcast_kernel<<<(n + 255) / 256, 256>>>(x, pXh, n);
    }
    wsplit_kernel<<<dim3(D / 32, D / 32), dim3(32, 8)>>>(wq, pWh, D, D);
    wsplit_kernel<<<dim3(KV_W / 32, D / 32), dim3(32, 8)>>>(
        wk, pWh + (size_t)4096 * D, D, KV_W);
    wsplit_kernel<<<dim3(KV_W / 32, D / 32), dim3(32, 8)>>>(
        wv, pWh + (size_t)5120 * D, D, KV_W);
    wsplit_kernel<<<dim3(D / 32, D / 32), dim3(32, 8)>>>(wo, pWoh, D, D);

    // combined QKV projection (single x single fp16 GEMM, N=6144)
    gemm_f16_kernel<<<dim3(QD / 128, S / 128), 256, GEMM1_SMEM>>>(
        pXh, pWh, pQKV, QD, D);

    // RoPE on Q; K rope + fp16 hi/lo split; V single fp16
    {
        int qn = S * HQ * (HD / 2);
        rope_q_kernel<<<(qn + 255) / 256, 256>>>(pQKV, cosv, sinv);
        int kvn = 2 * S * 512;
        kvsplit_kernel<<<(kvn + 255) / 256, 256>>>(pQKV, cosv, sinv, pKh, pKl, pVh);
    }

    // attention (compensated scores, single-fp16 PV; writes fp16 hi/lo)
    attn_mma_kernel<<<dim3(S / 64, HQ), 256, ATTN2_SMEM>>>(pQKV, pKh, pKl, pVh,
                                                           pXh, pXl);

    // output projection (2-term fp16 GEMM: A hi/lo compensated)
    gemm_f16x2_kernel<<<dim3(D / 128, S / 128), 256, GEMM_SMEM>>>(
        pXh, pXl, pWoh, out, D, D);
}